// round 13
// baseline (speedup 1.0000x reference)
#include <cuda_runtime.h>
#include <math.h>
#include <stdint.h>

#define BATCH   2
#define SEQ     4096
#define DMODEL  512
#define NHEADS  8
#define DK      64
#define DFF     2048
#define ROWS    (BATCH * SEQ)   // 8192
#define EPS     1e-5f

// ---------------- scratch (static device globals; no allocs allowed) ----------
__device__ float g_Q  [ROWS * DMODEL];
__device__ float g_K  [ROWS * DMODEL];
__device__ float g_V  [ROWS * DMODEL];
__device__ float g_AO [ROWS * DMODEL];
__device__ float g_X1 [ROWS * DMODEL];
__device__ float g_FFH[ROWS * DFF];
// rna-rounded weights, original layouts: Wq,Wk,Wv,Wo [512x512], W1 [512x2048], W2 [2048x512]
#define WSEG1 (DMODEL * DMODEL)          // 262144
#define WSEG2 (DMODEL * DFF)             // 1048576
__device__ float g_WT [4 * WSEG1 + 2 * WSEG2];

// ---------------- tf32 / async helpers ----------------------------------------
__device__ __forceinline__ float f2tf32(float x) {
    unsigned int r;
    asm("cvt.rna.tf32.f32 %0, %1;" : "=r"(r) : "f"(x));
    return __uint_as_float(r);
}

__device__ __forceinline__ float fex2(float x) {   // 2^x via MUFU.EX2
    float y;
    asm("ex2.approx.f32 %0, %1;" : "=f"(y) : "f"(x));
    return y;
}

__device__ __forceinline__ void mma_tf32(float* c,
                                         float a0, float a1, float a2, float a3,
                                         float b0, float b1)
{
    asm volatile(
        "mma.sync.aligned.m16n8k8.row.col.f32.tf32.tf32.f32 "
        "{%0,%1,%2,%3}, {%4,%5,%6,%7}, {%8,%9}, {%0,%1,%2,%3};"
        : "+f"(c[0]), "+f"(c[1]), "+f"(c[2]), "+f"(c[3])
        : "r"(__float_as_uint(a0)), "r"(__float_as_uint(a1)),
          "r"(__float_as_uint(a2)), "r"(__float_as_uint(a3)),
          "r"(__float_as_uint(b0)), "r"(__float_as_uint(b1)));
}

__device__ __forceinline__ void cp_async16(unsigned int smem_addr, const void* gptr) {
    asm volatile("cp.async.cg.shared.global [%0], [%1], 16;"
                 :: "r"(smem_addr), "l"(gptr));
}
#define CP_COMMIT() asm volatile("cp.async.commit_group;")
#define CP_WAIT0()  asm volatile("cp.async.wait_group 0;")
#define CP_WAIT1()  asm volatile("cp.async.wait_group 1;")

// ---------------- weight rounding: one fused pass over all six matrices -------
__global__ void __launch_bounds__(256)
wround(const float* __restrict__ Wq, const float* __restrict__ Wk,
       const float* __restrict__ Wv, const float* __restrict__ Wo,
       const float* __restrict__ W1, const float* __restrict__ W2,
       float* __restrict__ out)
{
    size_t i4 = ((size_t)blockIdx.x * 256 + threadIdx.x) * 4;
    const float* src;
    size_t off;
    if      (i4 < 1 * (size_t)WSEG1) { src = Wq; off = i4; }
    else if (i4 < 2 * (size_t)WSEG1) { src = Wk; off = i4 - 1 * (size_t)WSEG1; }
    else if (i4 < 3 * (size_t)WSEG1) { src = Wv; off = i4 - 2 * (size_t)WSEG1; }
    else if (i4 < 4 * (size_t)WSEG1) { src = Wo; off = i4 - 3 * (size_t)WSEG1; }
    else if (i4 < 4 * (size_t)WSEG1 + (size_t)WSEG2)
                                     { src = W1; off = i4 - 4 * (size_t)WSEG1; }
    else                             { src = W2; off = i4 - 4 * (size_t)WSEG1 - (size_t)WSEG2; }
    float4 v = *reinterpret_cast<const float4*>(src + off);
    float4 w = make_float4(f2tf32(v.x), f2tf32(v.y), f2tf32(v.z), f2tf32(v.w));
    *reinterpret_cast<float4*>(out + i4) = w;
}

// ---------------- tf32 tensor-core GEMM, 3-stage cp.async, depth-2 prefetch ---
// block tile 128x128x32, 256 threads, warps 2(m) x 4(n), warp tile 64x32
#define TBM 128
#define TBN 128
#define TBK 32
#define ASTR (TBK + 4)    // 36  -> A-frag pattern conflict-free
#define BSTR (TBN + 8)    // 136 -> B-frag pattern conflict-free
#define NSTG 3
#define STGF (TBM * ASTR + TBK * BSTR)            // floats per stage = 8960
#define GEMM_SMEM (NSTG * STGF * (int)sizeof(float))  // 107520 bytes

__device__ __forceinline__ void gemm_body(
    const float* __restrict__ A, const float* __restrict__ B,
    const float* __restrict__ bias, float* __restrict__ C,
    int N, int K, int relu, int row0, int col0)
{
    extern __shared__ float gsm[];

    const int tid  = threadIdx.x;
    const int warp = tid >> 5, lane = tid & 31;
    const int wm = warp >> 2;          // 0..1
    const int wn = warp & 3;           // 0..3
    const int r    = lane >> 2;        // 0..7
    const int cg   = lane & 3;         // 0..3

    // per-thread chunk coords (A: 128x32 = 1024 fl4; B: 32x128 = 1024 fl4; 4 each)
    int aRow[4], aCol[4], bRow[4], bCol[4];
    unsigned int aOffB[4], bOffB[4];   // byte offsets within one stage
    #pragma unroll
    for (int i = 0; i < 4; i++) {
        int l = tid + i * 256;
        aRow[i] = l >> 3;  aCol[i] = (l & 7) * 4;
        bRow[i] = l >> 5;  bCol[i] = (l & 31) * 4;
        aOffB[i] = (unsigned int)(aRow[i] * ASTR + aCol[i]) * 4u;
        bOffB[i] = (unsigned int)(TBM * ASTR + bRow[i] * BSTR + bCol[i]) * 4u;
    }
    const unsigned int smemBase = (unsigned int)__cvta_generic_to_shared(gsm);

    auto issue = [&](int stg, int k0) {
        unsigned int sb = smemBase + (unsigned int)(stg * STGF) * 4u;
        #pragma unroll
        for (int i = 0; i < 4; i++) {
            cp_async16(sb + aOffB[i], &A[(size_t)(row0 + aRow[i]) * K + k0 + aCol[i]]);
            cp_async16(sb + bOffB[i], &B[(size_t)(k0 + bRow[i]) * N + col0 + bCol[i]]);
        }
        CP_COMMIT();
    };

    float acc[4][4][4] = {};           // [mfrag][nfrag][c0..c3]

    const int NT = K / TBK;
    issue(0, 0);
    if (NT > 1) issue(1, TBK);

    for (int kt = 0; kt < NT; kt++) {
        const int cur = kt % NSTG;
        if (kt + 1 < NT) { CP_WAIT1(); } else { CP_WAIT0(); }
        __syncthreads();                 // tile kt resident; all warps past mma(kt-1)

        // depth-2 prefetch: stage (kt+2)%3 was last read at mma(kt-1) -> safe now
        if (kt + 2 < NT) issue((kt + 2) % NSTG, (kt + 2) * TBK);

        const float* As_ = gsm + cur * STGF;
        const float* Bs_ = As_ + TBM * ASTR;

        #pragma unroll
        for (int ks = 0; ks < 4; ks++) {
            const int kk = ks * 8;
            float a[4][4];
            #pragma unroll
            for (int mi = 0; mi < 4; mi++) {
                int mb = wm * 64 + mi * 16;
                a[mi][0] = As_[(mb + r    ) * ASTR + kk + cg    ];
                a[mi][1] = As_[(mb + r + 8) * ASTR + kk + cg    ];
                a[mi][2] = As_[(mb + r    ) * ASTR + kk + cg + 4];
                a[mi][3] = As_[(mb + r + 8) * ASTR + kk + cg + 4];
            }
            #pragma unroll
            for (int ni = 0; ni < 4; ni++) {
                int nb = wn * 32 + ni * 8;
                float b0 = Bs_[(kk + cg    ) * BSTR + nb + r];
                float b1 = Bs_[(kk + cg + 4) * BSTR + nb + r];
                #pragma unroll
                for (int mi = 0; mi < 4; mi++)
                    mma_tf32(acc[mi][ni], a[mi][0], a[mi][1], a[mi][2], a[mi][3], b0, b1);
            }
        }
    }

    // epilogue
    #pragma unroll
    for (int mi = 0; mi < 4; mi++) {
        int mb = row0 + wm * 64 + mi * 16;
        #pragma unroll
        for (int ni = 0; ni < 4; ni++) {
            int col = col0 + wn * 32 + ni * 8 + 2 * cg;
            float bs0 = bias[col], bs1 = bias[col + 1];
            #pragma unroll
            for (int half = 0; half < 2; half++) {
                int row = mb + r + half * 8;
                float v0 = acc[mi][ni][2 * half]     + bs0;
                float v1 = acc[mi][ni][2 * half + 1] + bs1;
                if (relu) { v0 = fmaxf(v0, 0.0f); v1 = fmaxf(v1, 0.0f); }
                *reinterpret_cast<float2*>(&C[(size_t)row * N + col]) = make_float2(v0, v1);
            }
        }
    }
}

__global__ void __launch_bounds__(256)
gemm_tc(const float* __restrict__ A, const float* __restrict__ B,
        const float* __restrict__ bias, float* __restrict__ C,
        int N, int K, int relu)
{
    gemm_body(A, B, bias, C, N, K, relu, blockIdx.y * TBM, blockIdx.x * TBN);
}

// fused QKV: grid.z in {0,1,2} selects projection
__global__ void __launch_bounds__(256)
qkv_tc(const float* __restrict__ x, const float* __restrict__ WT,
       const float* __restrict__ bq, const float* __restrict__ bk, const float* __restrict__ bv,
       float* __restrict__ Qo, float* __restrict__ Ko, float* __restrict__ Vo)
{
    const float* W  = WT + (size_t)blockIdx.z * WSEG1;
    const float* bb = (blockIdx.z == 0) ? bq : (blockIdx.z == 1) ? bk : bv;
    float*       O  = (blockIdx.z == 0) ? Qo : (blockIdx.z == 1) ? Ko : Vo;
    gemm_body(x, W, bb, O, DMODEL, DMODEL, 0, blockIdx.y * TBM, blockIdx.x * TBN);
}

// ---------------- flash attention (R9, unchanged) ------------------------------
#define QTILE 128
#define KTILE 64
#define QSTR 68
#define VSTR 72
#define ATT_SMEM ((QTILE * QSTR + KTILE * QSTR + KTILE * VSTR + QTILE * QSTR) * (int)sizeof(float))
#define QSCALE 0.18033688011f   // 0.125 * log2(e)

__global__ void __launch_bounds__(128)
attn_tc(const float* __restrict__ Q, const float* __restrict__ K,
        const float* __restrict__ V, float* __restrict__ O)
{
    extern __shared__ float sh[];
    float* Qs = sh;                      // [128][68]
    float* Ks = Qs + QTILE * QSTR;       // [64][68]
    float* Vs = Ks + KTILE * QSTR;       // [64][72]
    float* Ps = Vs + KTILE * VSTR;       // [128][68]

    const int tid  = threadIdx.x;
    const int warp = tid >> 5, lane = tid & 31;
    const int r    = lane >> 2;
    const int cg   = lane & 3;
    const int wb   = warp * 32;

    const int qt = blockIdx.x;
    const int bh = blockIdx.y;
    const int b  = bh >> 3, h = bh & 7;
    const int base = b * SEQ;
    const int q0   = base + qt * QTILE;
    const int colh = h * DK;

    int kvRow[8], kvC4[8];
    unsigned int ksAddr[8], vsAddr[8];
    #pragma unroll
    for (int i = 0; i < 8; i++) {
        int l = tid + i * 128;
        kvRow[i] = l >> 4;
        kvC4[i]  = (l & 15) * 4;
        ksAddr[i] = (unsigned int)__cvta_generic_to_shared(&Ks[kvRow[i] * QSTR + kvC4[i]]);
        vsAddr[i] = (unsigned int)__cvta_generic_to_shared(&Vs[kvRow[i] * VSTR + kvC4[i]]);
    }

    #pragma unroll
    for (int i = 0; i < 8; i++)
        cp_async16(ksAddr[i], &K[(size_t)(base + kvRow[i]) * DMODEL + colh + kvC4[i]]);
    CP_COMMIT();

    #pragma unroll
    for (int i = 0; i < 16; i++) {
        int l   = tid + i * 128;
        int row = l >> 4;
        int c4  = (l & 15) * 4;
        float4 v = *reinterpret_cast<const float4*>(&Q[(size_t)(q0 + row) * DMODEL + colh + c4]);
        float4 w = make_float4(f2tf32(QSCALE * v.x), f2tf32(QSCALE * v.y),
                               f2tf32(QSCALE * v.z), f2tf32(QSCALE * v.w));
        *reinterpret_cast<float4*>(&Qs[row * QSTR + c4]) = w;
    }

    float o[2][8][4] = {};
    float rmax[2][2], rsum[2][2];
    #pragma unroll
    for (int mf = 0; mf < 2; mf++)
        #pragma unroll
        for (int z = 0; z < 2; z++) { rmax[mf][z] = -1e30f; rsum[mf][z] = 0.0f; }

    for (int j0 = 0; j0 < SEQ; j0 += KTILE) {
        const int kr = base + j0;

        CP_WAIT0();
        __syncthreads();                 // Ks(j) ready; everyone past PV(j-1)

        #pragma unroll
        for (int i = 0; i < 8; i++)
            cp_async16(vsAddr[i], &V[(size_t)(kr + kvRow[i]) * DMODEL + colh + kvC4[i]]);
        CP_COMMIT();

        float s[2][8][4] = {};
        #pragma unroll
        for (int kk8 = 0; kk8 < 8; kk8++) {
            const int kk = kk8 * 8;
            float a[2][4];
            #pragma unroll
            for (int mf = 0; mf < 2; mf++) {
                int mb = wb + mf * 16;
                a[mf][0] = Qs[(mb + r    ) * QSTR + kk + cg    ];
                a[mf][1] = Qs[(mb + r + 8) * QSTR + kk + cg    ];
                a[mf][2] = Qs[(mb + r    ) * QSTR + kk + cg + 4];
                a[mf][3] = Qs[(mb + r + 8) * QSTR + kk + cg + 4];
            }
            #pragma unroll
            for (int ni = 0; ni < 8; ni++) {
                float b0 = Ks[(ni * 8 + r) * QSTR + kk + cg    ];
                float b1 = Ks[(ni * 8 + r) * QSTR + kk + cg + 4];
                mma_tf32(s[0][ni], a[0][0], a[0][1], a[0][2], a[0][3], b0, b1);
                mma_tf32(s[1][ni], a[1][0], a[1][1], a[1][2], a[1][3], b0, b1);
            }
        }

        // online softmax (log2 domain; overlaps V(j) DMA in flight)
        #pragma unroll
        for (int mf = 0; mf < 2; mf++) {
            #pragma unroll
            for (int z = 0; z < 2; z++) {
                float mx = -1e30f;
                #pragma unroll
                for (int ni = 0; ni < 8; ni++)
                    mx = fmaxf(mx, fmaxf(s[mf][ni][2 * z], s[mf][ni][2 * z + 1]));
                mx = fmaxf(mx, __shfl_xor_sync(0xffffffffu, mx, 1));
                mx = fmaxf(mx, __shfl_xor_sync(0xffffffffu, mx, 2));
                float nm   = fmaxf(rmax[mf][z], mx);
                float corr = fex2(rmax[mf][z] - nm);
                rmax[mf][z] = nm;
                float ps = 0.0f;
                #pragma unroll
                for (int ni = 0; ni < 8; ni++) {
                    float e0 = fex2(s[mf][ni][2 * z]     - nm);
                    float e1 = fex2(s[mf][ni][2 * z + 1] - nm);
                    s[mf][ni][2 * z] = e0; s[mf][ni][2 * z + 1] = e1;
                    ps += e0 + e1;
                }
                ps += __shfl_xor_sync(0xffffffffu, ps, 1);
                ps += __shfl_xor_sync(0xffffffffu, ps, 2);
                rsum[mf][z] = rsum[mf][z] * corr + ps;
                #pragma unroll
                for (int ni = 0; ni < 8; ni++) {
                    o[mf][ni][2 * z]     *= corr;
                    o[mf][ni][2 * z + 1] *= corr;
                }
            }
        }

        CP_WAIT0();
        __syncthreads();                 // Vs(j) ready; all warps done reading Ks(j)

        #pragma unroll
        for (int mf = 0; mf < 2; mf++) {
            #pragma unroll
            for (int ni = 0; ni < 8; ni++) {
                int col = ni * 8 + 2 * cg;
                #pragma unroll
                for (int z = 0; z < 2; z++) {
                    int row = wb + mf * 16 + r + z * 8;
                    *reinterpret_cast<float2*>(&Ps[row * QSTR + col]) =
                        make_float2(f2tf32(s[mf][ni][2 * z]), f2tf32(s[mf][ni][2 * z + 1]));
                }
            }
        }
        __syncwarp();   // P written/read within the same warp's rows only

        if (j0 + KTILE < SEQ) {
            #pragma unroll
            for (int i = 0; i < 8; i++)
                cp_async16(ksAddr[i], &K[(size_t)(kr + KTILE + kvRow[i]) * DMODEL + colh + kvC4[i]]);
            CP_COMMIT();
        }

        #pragma unroll
        for (int kk8 = 0; kk8 < 8; kk8++) {
            const int kk = kk8 * 8;
            float a[2][4];
            #pragma unroll
            for (int mf = 0; mf < 2; mf++) {
                int mb = wb + mf * 16;
                a[mf][0] = Ps[(mb + r    ) * QSTR + kk + cg    ];
                a[mf][1] = Ps[(mb + r + 8) * QSTR + kk + cg    ];
                a[mf][2] = Ps[(mb + r    ) * QSTR + kk + cg + 4];
                a[mf][3] = Ps[(mb + r + 8) * QSTR + kk + cg + 4];
            }
            #pragma unroll
            for (int ni = 0; ni < 8; ni++) {
                float b0 = Vs[(kk + cg    ) * VSTR + ni * 8 + r];
                float b1 = Vs[(kk + cg + 4) * VSTR + ni * 8 + r];
                mma_tf32(o[0][ni], a[0][0], a[0][1], a[0][2], a[0][3], b0, b1);
                mma_tf32(o[1][ni], a[1][0], a[1][1], a[1][2], a[1][3], b0, b1);
            }
        }
    }

    #pragma unroll
    for (int mf = 0; mf < 2; mf++) {
        #pragma unroll
        for (int z = 0; z < 2; z++) {
            float inv = 1.0f / rsum[mf][z];
            int row = q0 + wb + mf * 16 + r + z * 8;
            #pragma unroll
            for (int ni = 0; ni < 8; ni++) {
                int col = colh + ni * 8 + 2 * cg;
                *reinterpret_cast<float2*>(&O[(size_t)row * DMODEL + col]) =
                    make_float2(o[mf][ni][2 * z] * inv, o[mf][ni][2 * z + 1] * inv);
            }
        }
    }
}

// ---------------- residual add + layernorm (reference form: /(std+eps)) -------
__global__ void __launch_bounds__(128)
add_ln_kernel(const float* __restrict__ A, const float* __restrict__ Bv,
              const float* __restrict__ gamma, const float* __restrict__ beta,
              float* __restrict__ out)
{
    const int row = blockIdx.x;
    const int tid = threadIdx.x;
    __shared__ float red[4];

    const float4 a4 = reinterpret_cast<const float4*>(A  + (size_t)row * DMODEL)[tid];
    const float4 b4 = reinterpret_cast<const float4*>(Bv + (size_t)row * DMODEL)[tid];
    float x0 = a4.x + b4.x, x1 = a4.y + b4.y, x2 = a4.z + b4.z, x3 = a4.w + b4.w;

    float s = x0 + x1 + x2 + x3;
    #pragma unroll
    for (int off = 16; off; off >>= 1) s += __shfl_xor_sync(0xffffffffu, s, off);
    if ((tid & 31) == 0) red[tid >> 5] = s;
    __syncthreads();
    s = red[0] + red[1] + red[2] + red[3];
    const float mean = s * (1.0f / DMODEL);

    float d0 = x0 - mean, d1 = x1 - mean, d2 = x2 - mean, d3 = x3 - mean;
    float v = d0 * d0 + d1 * d1 + d2 * d2 + d3 * d3;
    #pragma unroll
    for (int off = 16; off; off >>= 1) v += __shfl_xor_sync(0xffffffffu, v, off);
    __syncthreads();
    if ((tid & 31) == 0) red[tid >> 5] = v;
    __syncthreads();
    v = (red[0] + red[1] + red[2] + red[3]) * (1.0f / DMODEL);

    const float inv = 1.0f / (sqrtf(v) + EPS);
    const float4 g4  = reinterpret_cast<const float4*>(gamma)[tid];
    const float4 be4 = reinterpret_cast<const float4*>(beta )[tid];
    float4 o4;
    o4.x = d0 * inv * g4.x + be4.x;
    o4.y = d1 * inv * g4.y + be4.y;
    o4.z = d2 * inv * g4.z + be4.z;
    o4.w = d3 * inv * g4.w + be4.w;
    reinterpret_cast<float4*>(out + (size_t)row * DMODEL)[tid] = o4;
}

// ---------------- host launch --------------------------------------------------
extern "C" void kernel_launch(void* const* d_in, const int* in_sizes, int n_in,
                              void* d_out, int out_size)
{
    const float* x   = (const float*)d_in[0];
    const float* Wq  = (const float*)d_in[1];
    const float* bq  = (const float*)d_in[2];
    const float* Wk  = (const float*)d_in[3];
    const float* bk  = (const float*)d_in[4];
    const float* Wv  = (const float*)d_in[5];
    const float* bv  = (const float*)d_in[6];
    const float* Wo  = (const float*)d_in[7];
    const float* bo  = (const float*)d_in[8];
    const float* W1  = (const float*)d_in[9];
    const float* b1  = (const float*)d_in[10];
    const float* W2  = (const float*)d_in[11];
    const float* b2  = (const float*)d_in[12];
    const float* g1  = (const float*)d_in[13];
    const float* be1 = (const float*)d_in[14];
    const float* g2  = (const float*)d_in[15];
    const float* be2 = (const float*)d_in[16];
    float* out = (float*)d_out;

    float *Qp, *Kp, *Vp, *AOp, *X1p, *FFHp, *WTp;
    cudaGetSymbolAddress((void**)&Qp,   g_Q);
    cudaGetSymbolAddress((void**)&Kp,   g_K);
    cudaGetSymbolAddress((void**)&Vp,   g_V);
    cudaGetSymbolAddress((void**)&AOp,  g_AO);
    cudaGetSymbolAddress((void**)&X1p,  g_X1);
    cudaGetSymbolAddress((void**)&FFHp, g_FFH);
    cudaGetSymbolAddress((void**)&WTp,  g_WT);

    const float* Wor = WTp + 3 * WSEG1;
    const float* W1r = WTp + 4 * WSEG1;
    const float* W2r = WTp + 4 * WSEG1 + WSEG2;

    cudaFuncSetAttribute(attn_tc, cudaFuncAttributeMaxDynamicSharedMemorySize, ATT_SMEM);
    cudaFuncSetAttribute(gemm_tc, cudaFuncAttributeMaxDynamicSharedMemorySize, GEMM_SMEM);
    cudaFuncSetAttribute(qkv_tc,  cudaFuncAttributeMaxDynamicSharedMemorySize, GEMM_SMEM);

    const dim3 t256(256), t128(128);
    const dim3 gQKV (DMODEL / TBN, ROWS / TBM, 3); // (4, 64, 3)
    const dim3 gProj(DMODEL / TBN, ROWS / TBM);    // (4, 64)
    const dim3 gFF1 (DFF    / TBN, ROWS / TBM);    // (16, 64)

    // round all weights to tf32 (rna) in one pass
    const int wtotal4 = (4 * WSEG1 + 2 * WSEG2) / 4;    // 786432 float4s
    wround<<<wtotal4 / 256, t256>>>(Wq, Wk, Wv, Wo, W1, W2, WTp);

    // QKV projections (fused launch, rounded weights)
    qkv_tc<<<gQKV, t256, GEMM_SMEM>>>(x, WTp, bq, bk, bv, Qp, Kp, Vp);

    // attention
    attn_tc<<<dim3(SEQ / QTILE, BATCH * NHEADS), t128, ATT_SMEM>>>(Qp, Kp, Vp, AOp);

    // output projection + LN1
    gemm_tc<<<gProj, t256, GEMM_SMEM>>>(AOp, Wor, bo, Qp, DMODEL, DMODEL, 0);
    add_ln_kernel<<<ROWS, 128>>>(x, Qp, g1, be1, X1p);

    // FFN
    gemm_tc<<<gFF1,  t256, GEMM_SMEM>>>(X1p,  W1r, b1, FFHp, DFF,    DMODEL, 1);
    gemm_tc<<<gProj, t256, GEMM_SMEM>>>(FFHp, W2r, b2, Kp,   DMODEL, DFF,    0);

    // LN2 -> final output
    add_ln_kernel<<<ROWS, 128>>>(X1p, Kp, g2, be2, out);
}

// round 14
// speedup vs baseline: 1.0501x; 1.0501x over previous
#include <cuda_runtime.h>
#include <math.h>
#include <stdint.h>

#define BATCH   2
#define SEQ     4096
#define DMODEL  512
#define NHEADS  8
#define DK      64
#define DFF     2048
#define ROWS    (BATCH * SEQ)   // 8192
#define EPS     1e-5f

// ---------------- scratch (static device globals; no allocs allowed) ----------
__device__ float g_Q  [ROWS * DMODEL];
__device__ float g_K  [ROWS * DMODEL];
__device__ float g_V  [ROWS * DMODEL];
__device__ float g_AO [ROWS * DMODEL];
__device__ float g_X1 [ROWS * DMODEL];
__device__ float g_FFH[ROWS * DFF];
// rna-rounded weights, original layouts: Wq,Wk,Wv,Wo [512x512], W1 [512x2048], W2 [2048x512]
#define WSEG1 (DMODEL * DMODEL)          // 262144
#define WSEG2 (DMODEL * DFF)             // 1048576
__device__ float g_WT [4 * WSEG1 + 2 * WSEG2];

// ---------------- tf32 / async helpers ----------------------------------------
__device__ __forceinline__ float f2tf32(float x) {
    unsigned int r;
    asm("cvt.rna.tf32.f32 %0, %1;" : "=r"(r) : "f"(x));
    return __uint_as_float(r);
}

__device__ __forceinline__ float fex2(float x) {   // 2^x via MUFU.EX2
    float y;
    asm("ex2.approx.f32 %0, %1;" : "=f"(y) : "f"(x));
    return y;
}

__device__ __forceinline__ void mma_tf32(float* c,
                                         float a0, float a1, float a2, float a3,
                                         float b0, float b1)
{
    asm volatile(
        "mma.sync.aligned.m16n8k8.row.col.f32.tf32.tf32.f32 "
        "{%0,%1,%2,%3}, {%4,%5,%6,%7}, {%8,%9}, {%0,%1,%2,%3};"
        : "+f"(c[0]), "+f"(c[1]), "+f"(c[2]), "+f"(c[3])
        : "r"(__float_as_uint(a0)), "r"(__float_as_uint(a1)),
          "r"(__float_as_uint(a2)), "r"(__float_as_uint(a3)),
          "r"(__float_as_uint(b0)), "r"(__float_as_uint(b1)));
}

__device__ __forceinline__ void cp_async16(unsigned int smem_addr, const void* gptr) {
    asm volatile("cp.async.cg.shared.global [%0], [%1], 16;"
                 :: "r"(smem_addr), "l"(gptr));
}
#define CP_COMMIT() asm volatile("cp.async.commit_group;")
#define CP_WAIT0()  asm volatile("cp.async.wait_group 0;")

// ---------------- weight rounding: one fused pass over all six matrices -------
__global__ void __launch_bounds__(256)
wround(const float* __restrict__ Wq, const float* __restrict__ Wk,
       const float* __restrict__ Wv, const float* __restrict__ Wo,
       const float* __restrict__ W1, const float* __restrict__ W2,
       float* __restrict__ out)
{
    size_t i4 = ((size_t)blockIdx.x * 256 + threadIdx.x) * 4;
    const float* src;
    size_t off;
    if      (i4 < 1 * (size_t)WSEG1) { src = Wq; off = i4; }
    else if (i4 < 2 * (size_t)WSEG1) { src = Wk; off = i4 - 1 * (size_t)WSEG1; }
    else if (i4 < 3 * (size_t)WSEG1) { src = Wv; off = i4 - 2 * (size_t)WSEG1; }
    else if (i4 < 4 * (size_t)WSEG1) { src = Wo; off = i4 - 3 * (size_t)WSEG1; }
    else if (i4 < 4 * (size_t)WSEG1 + (size_t)WSEG2)
                                     { src = W1; off = i4 - 4 * (size_t)WSEG1; }
    else                             { src = W2; off = i4 - 4 * (size_t)WSEG1 - (size_t)WSEG2; }
    float4 v = *reinterpret_cast<const float4*>(src + off);
    float4 w = make_float4(f2tf32(v.x), f2tf32(v.y), f2tf32(v.z), f2tf32(v.w));
    *reinterpret_cast<float4*>(out + i4) = w;
}

// ---------------- tf32 tensor-core GEMM, 2-stage cp.async, 2 CTAs/SM ----------
// block tile 128x128x32, 256 threads, warps 2(m) x 4(n), warp tile 64x32
#define TBM 128
#define TBN 128
#define TBK 32
#define ASTR (TBK + 4)    // 36  -> A-frag pattern conflict-free
#define BSTR (TBN + 8)    // 136 -> B-frag pattern conflict-free
#define NSTG 2
#define STGF (TBM * ASTR + TBK * BSTR)            // floats per stage = 8960
#define GEMM_SMEM (NSTG * STGF * (int)sizeof(float))  // 71680 bytes -> 2 CTAs/SM

__device__ __forceinline__ void gemm_body(
    const float* __restrict__ A, const float* __restrict__ B,
    const float* __restrict__ bias, float* __restrict__ C,
    int N, int K, int relu, int row0, int col0)
{
    extern __shared__ float gsm[];

    const int tid  = threadIdx.x;
    const int warp = tid >> 5, lane = tid & 31;
    const int wm = warp >> 2;          // 0..1
    const int wn = warp & 3;           // 0..3
    const int r    = lane >> 2;        // 0..7
    const int cg   = lane & 3;         // 0..3

    // per-thread chunk coords (A: 128x32 = 1024 fl4; B: 32x128 = 1024 fl4; 4 each)
    int aRow[4], aCol[4], bRow[4], bCol[4];
    unsigned int aOffB[4], bOffB[4];   // byte offsets within one stage
    #pragma unroll
    for (int i = 0; i < 4; i++) {
        int l = tid + i * 256;
        aRow[i] = l >> 3;  aCol[i] = (l & 7) * 4;
        bRow[i] = l >> 5;  bCol[i] = (l & 31) * 4;
        aOffB[i] = (unsigned int)(aRow[i] * ASTR + aCol[i]) * 4u;
        bOffB[i] = (unsigned int)(TBM * ASTR + bRow[i] * BSTR + bCol[i]) * 4u;
    }
    const unsigned int smemBase = (unsigned int)__cvta_generic_to_shared(gsm);

    auto issue = [&](int stg, int k0) {
        unsigned int sb = smemBase + (unsigned int)(stg * STGF) * 4u;
        #pragma unroll
        for (int i = 0; i < 4; i++) {
            cp_async16(sb + aOffB[i], &A[(size_t)(row0 + aRow[i]) * K + k0 + aCol[i]]);
            cp_async16(sb + bOffB[i], &B[(size_t)(k0 + bRow[i]) * N + col0 + bCol[i]]);
        }
        CP_COMMIT();
    };

    float acc[4][4][4] = {};           // [mfrag][nfrag][c0..c3]

    const int NT = K / TBK;
    issue(0, 0);

    for (int kt = 0; kt < NT; kt++) {
        const int cur = kt & 1;
        CP_WAIT0();                      // tile kt resident in stage cur
        __syncthreads();                 // all warps past mma(kt-1) (stage cur^1 free)

        if (kt + 1 < NT) issue(cur ^ 1, (kt + 1) * TBK);   // overlaps mma below

        const float* As_ = gsm + cur * STGF;
        const float* Bs_ = As_ + TBM * ASTR;

        #pragma unroll
        for (int ks = 0; ks < 4; ks++) {
            const int kk = ks * 8;
            float a[4][4];
            #pragma unroll
            for (int mi = 0; mi < 4; mi++) {
                int mb = wm * 64 + mi * 16;
                a[mi][0] = As_[(mb + r    ) * ASTR + kk + cg    ];
                a[mi][1] = As_[(mb + r + 8) * ASTR + kk + cg    ];
                a[mi][2] = As_[(mb + r    ) * ASTR + kk + cg + 4];
                a[mi][3] = As_[(mb + r + 8) * ASTR + kk + cg + 4];
            }
            #pragma unroll
            for (int ni = 0; ni < 4; ni++) {
                int nb = wn * 32 + ni * 8;
                float b0 = Bs_[(kk + cg    ) * BSTR + nb + r];
                float b1 = Bs_[(kk + cg + 4) * BSTR + nb + r];
                #pragma unroll
                for (int mi = 0; mi < 4; mi++)
                    mma_tf32(acc[mi][ni], a[mi][0], a[mi][1], a[mi][2], a[mi][3], b0, b1);
            }
        }
    }

    // epilogue
    #pragma unroll
    for (int mi = 0; mi < 4; mi++) {
        int mb = row0 + wm * 64 + mi * 16;
        #pragma unroll
        for (int ni = 0; ni < 4; ni++) {
            int col = col0 + wn * 32 + ni * 8 + 2 * cg;
            float bs0 = bias[col], bs1 = bias[col + 1];
            #pragma unroll
            for (int half = 0; half < 2; half++) {
                int row = mb + r + half * 8;
                float v0 = acc[mi][ni][2 * half]     + bs0;
                float v1 = acc[mi][ni][2 * half + 1] + bs1;
                if (relu) { v0 = fmaxf(v0, 0.0f); v1 = fmaxf(v1, 0.0f); }
                *reinterpret_cast<float2*>(&C[(size_t)row * N + col]) = make_float2(v0, v1);
            }
        }
    }
}

__global__ void __launch_bounds__(256, 2)
gemm_tc(const float* __restrict__ A, const float* __restrict__ B,
        const float* __restrict__ bias, float* __restrict__ C,
        int N, int K, int relu)
{
    gemm_body(A, B, bias, C, N, K, relu, blockIdx.y * TBM, blockIdx.x * TBN);
}

// fused QKV: grid.z in {0,1,2} selects projection
__global__ void __launch_bounds__(256, 2)
qkv_tc(const float* __restrict__ x, const float* __restrict__ WT,
       const float* __restrict__ bq, const float* __restrict__ bk, const float* __restrict__ bv,
       float* __restrict__ Qo, float* __restrict__ Ko, float* __restrict__ Vo)
{
    const float* W  = WT + (size_t)blockIdx.z * WSEG1;
    const float* bb = (blockIdx.z == 0) ? bq : (blockIdx.z == 1) ? bk : bv;
    float*       O  = (blockIdx.z == 0) ? Qo : (blockIdx.z == 1) ? Ko : Vo;
    gemm_body(x, W, bb, O, DMODEL, DMODEL, 0, blockIdx.y * TBM, blockIdx.x * TBN);
}

// ---------------- flash attention (R9, unchanged) ------------------------------
#define QTILE 128
#define KTILE 64
#define QSTR 68
#define VSTR 72
#define ATT_SMEM ((QTILE * QSTR + KTILE * QSTR + KTILE * VSTR + QTILE * QSTR) * (int)sizeof(float))
#define QSCALE 0.18033688011f   // 0.125 * log2(e)

__global__ void __launch_bounds__(128)
attn_tc(const float* __restrict__ Q, const float* __restrict__ K,
        const float* __restrict__ V, float* __restrict__ O)
{
    extern __shared__ float sh[];
    float* Qs = sh;                      // [128][68]
    float* Ks = Qs + QTILE * QSTR;       // [64][68]
    float* Vs = Ks + KTILE * QSTR;       // [64][72]
    float* Ps = Vs + KTILE * VSTR;       // [128][68]

    const int tid  = threadIdx.x;
    const int warp = tid >> 5, lane = tid & 31;
    const int r    = lane >> 2;
    const int cg   = lane & 3;
    const int wb   = warp * 32;

    const int qt = blockIdx.x;
    const int bh = blockIdx.y;
    const int b  = bh >> 3, h = bh & 7;
    const int base = b * SEQ;
    const int q0   = base + qt * QTILE;
    const int colh = h * DK;

    int kvRow[8], kvC4[8];
    unsigned int ksAddr[8], vsAddr[8];
    #pragma unroll
    for (int i = 0; i < 8; i++) {
        int l = tid + i * 128;
        kvRow[i] = l >> 4;
        kvC4[i]  = (l & 15) * 4;
        ksAddr[i] = (unsigned int)__cvta_generic_to_shared(&Ks[kvRow[i] * QSTR + kvC4[i]]);
        vsAddr[i] = (unsigned int)__cvta_generic_to_shared(&Vs[kvRow[i] * VSTR + kvC4[i]]);
    }

    #pragma unroll
    for (int i = 0; i < 8; i++)
        cp_async16(ksAddr[i], &K[(size_t)(base + kvRow[i]) * DMODEL + colh + kvC4[i]]);
    CP_COMMIT();

    #pragma unroll
    for (int i = 0; i < 16; i++) {
        int l   = tid + i * 128;
        int row = l >> 4;
        int c4  = (l & 15) * 4;
        float4 v = *reinterpret_cast<const float4*>(&Q[(size_t)(q0 + row) * DMODEL + colh + c4]);
        float4 w = make_float4(f2tf32(QSCALE * v.x), f2tf32(QSCALE * v.y),
                               f2tf32(QSCALE * v.z), f2tf32(QSCALE * v.w));
        *reinterpret_cast<float4*>(&Qs[row * QSTR + c4]) = w;
    }

    float o[2][8][4] = {};
    float rmax[2][2], rsum[2][2];
    #pragma unroll
    for (int mf = 0; mf < 2; mf++)
        #pragma unroll
        for (int z = 0; z < 2; z++) { rmax[mf][z] = -1e30f; rsum[mf][z] = 0.0f; }

    for (int j0 = 0; j0 < SEQ; j0 += KTILE) {
        const int kr = base + j0;

        CP_WAIT0();
        __syncthreads();                 // Ks(j) ready; everyone past PV(j-1)

        #pragma unroll
        for (int i = 0; i < 8; i++)
            cp_async16(vsAddr[i], &V[(size_t)(kr + kvRow[i]) * DMODEL + colh + kvC4[i]]);
        CP_COMMIT();

        float s[2][8][4] = {};
        #pragma unroll
        for (int kk8 = 0; kk8 < 8; kk8++) {
            const int kk = kk8 * 8;
            float a[2][4];
            #pragma unroll
            for (int mf = 0; mf < 2; mf++) {
                int mb = wb + mf * 16;
                a[mf][0] = Qs[(mb + r    ) * QSTR + kk + cg    ];
                a[mf][1] = Qs[(mb + r + 8) * QSTR + kk + cg    ];
                a[mf][2] = Qs[(mb + r    ) * QSTR + kk + cg + 4];
                a[mf][3] = Qs[(mb + r + 8) * QSTR + kk + cg + 4];
            }
            #pragma unroll
            for (int ni = 0; ni < 8; ni++) {
                float b0 = Ks[(ni * 8 + r) * QSTR + kk + cg    ];
                float b1 = Ks[(ni * 8 + r) * QSTR + kk + cg + 4];
                mma_tf32(s[0][ni], a[0][0], a[0][1], a[0][2], a[0][3], b0, b1);
                mma_tf32(s[1][ni], a[1][0], a[1][1], a[1][2], a[1][3], b0, b1);
            }
        }

        // online softmax (log2 domain; overlaps V(j) DMA in flight)
        #pragma unroll
        for (int mf = 0; mf < 2; mf++) {
            #pragma unroll
            for (int z = 0; z < 2; z++) {
                float mx = -1e30f;
                #pragma unroll
                for (int ni = 0; ni < 8; ni++)
                    mx = fmaxf(mx, fmaxf(s[mf][ni][2 * z], s[mf][ni][2 * z + 1]));
                mx = fmaxf(mx, __shfl_xor_sync(0xffffffffu, mx, 1));
                mx = fmaxf(mx, __shfl_xor_sync(0xffffffffu, mx, 2));
                float nm   = fmaxf(rmax[mf][z], mx);
                float corr = fex2(rmax[mf][z] - nm);
                rmax[mf][z] = nm;
                float ps = 0.0f;
                #pragma unroll
                for (int ni = 0; ni < 8; ni++) {
                    float e0 = fex2(s[mf][ni][2 * z]     - nm);
                    float e1 = fex2(s[mf][ni][2 * z + 1] - nm);
                    s[mf][ni][2 * z] = e0; s[mf][ni][2 * z + 1] = e1;
                    ps += e0 + e1;
                }
                ps += __shfl_xor_sync(0xffffffffu, ps, 1);
                ps += __shfl_xor_sync(0xffffffffu, ps, 2);
                rsum[mf][z] = rsum[mf][z] * corr + ps;
                #pragma unroll
                for (int ni = 0; ni < 8; ni++) {
                    o[mf][ni][2 * z]     *= corr;
                    o[mf][ni][2 * z + 1] *= corr;
                }
            }
        }

        CP_WAIT0();
        __syncthreads();                 // Vs(j) ready; all warps done reading Ks(j)

        #pragma unroll
        for (int mf = 0; mf < 2; mf++) {
            #pragma unroll
            for (int ni = 0; ni < 8; ni++) {
                int col = ni * 8 + 2 * cg;
                #pragma unroll
                for (int z = 0; z < 2; z++) {
                    int row = wb + mf * 16 + r + z * 8;
                    *reinterpret_cast<float2*>(&Ps[row * QSTR + col]) =
                        make_float2(f2tf32(s[mf][ni][2 * z]), f2tf32(s[mf][ni][2 * z + 1]));
                }
            }
        }
        __syncwarp();   // P written/read within the same warp's rows only

        if (j0 + KTILE < SEQ) {
            #pragma unroll
            for (int i = 0; i < 8; i++)
                cp_async16(ksAddr[i], &K[(size_t)(kr + KTILE + kvRow[i]) * DMODEL + colh + kvC4[i]]);
            CP_COMMIT();
        }

        #pragma unroll
        for (int kk8 = 0; kk8 < 8; kk8++) {
            const int kk = kk8 * 8;
            float a[2][4];
            #pragma unroll
            for (int mf = 0; mf < 2; mf++) {
                int mb = wb + mf * 16;
                a[mf][0] = Ps[(mb + r    ) * QSTR + kk + cg    ];
                a[mf][1] = Ps[(mb + r + 8) * QSTR + kk + cg    ];
                a[mf][2] = Ps[(mb + r    ) * QSTR + kk + cg + 4];
                a[mf][3] = Ps[(mb + r + 8) * QSTR + kk + cg + 4];
            }
            #pragma unroll
            for (int ni = 0; ni < 8; ni++) {
                float b0 = Vs[(kk + cg    ) * VSTR + ni * 8 + r];
                float b1 = Vs[(kk + cg + 4) * VSTR + ni * 8 + r];
                mma_tf32(o[0][ni], a[0][0], a[0][1], a[0][2], a[0][3], b0, b1);
                mma_tf32(o[1][ni], a[1][0], a[1][1], a[1][2], a[1][3], b0, b1);
            }
        }
    }

    #pragma unroll
    for (int mf = 0; mf < 2; mf++) {
        #pragma unroll
        for (int z = 0; z < 2; z++) {
            float inv = 1.0f / rsum[mf][z];
            int row = q0 + wb + mf * 16 + r + z * 8;
            #pragma unroll
            for (int ni = 0; ni < 8; ni++) {
                int col = colh + ni * 8 + 2 * cg;
                *reinterpret_cast<float2*>(&O[(size_t)row * DMODEL + col]) =
                    make_float2(o[mf][ni][2 * z] * inv, o[mf][ni][2 * z + 1] * inv);
            }
        }
    }
}

// ---------------- residual add + layernorm (reference form: /(std+eps)) -------
__global__ void __launch_bounds__(128)
add_ln_kernel(const float* __restrict__ A, const float* __restrict__ Bv,
              const float* __restrict__ gamma, const float* __restrict__ beta,
              float* __restrict__ out)
{
    const int row = blockIdx.x;
    const int tid = threadIdx.x;
    __shared__ float red[4];

    const float4 a4 = reinterpret_cast<const float4*>(A  + (size_t)row * DMODEL)[tid];
    const float4 b4 = reinterpret_cast<const float4*>(Bv + (size_t)row * DMODEL)[tid];
    float x0 = a4.x + b4.x, x1 = a4.y + b4.y, x2 = a4.z + b4.z, x3 = a4.w + b4.w;

    float s = x0 + x1 + x2 + x3;
    #pragma unroll
    for (int off = 16; off; off >>= 1) s += __shfl_xor_sync(0xffffffffu, s, off);
    if ((tid & 31) == 0) red[tid >> 5] = s;
    __syncthreads();
    s = red[0] + red[1] + red[2] + red[3];
    const float mean = s * (1.0f / DMODEL);

    float d0 = x0 - mean, d1 = x1 - mean, d2 = x2 - mean, d3 = x3 - mean;
    float v = d0 * d0 + d1 * d1 + d2 * d2 + d3 * d3;
    #pragma unroll
    for (int off = 16; off; off >>= 1) v += __shfl_xor_sync(0xffffffffu, v, off);
    __syncthreads();
    if ((tid & 31) == 0) red[tid >> 5] = v;
    __syncthreads();
    v = (red[0] + red[1] + red[2] + red[3]) * (1.0f / DMODEL);

    const float inv = 1.0f / (sqrtf(v) + EPS);
    const float4 g4  = reinterpret_cast<const float4*>(gamma)[tid];
    const float4 be4 = reinterpret_cast<const float4*>(beta )[tid];
    float4 o4;
    o4.x = d0 * inv * g4.x + be4.x;
    o4.y = d1 * inv * g4.y + be4.y;
    o4.z = d2 * inv * g4.z + be4.z;
    o4.w = d3 * inv * g4.w + be4.w;
    reinterpret_cast<float4*>(out + (size_t)row * DMODEL)[tid] = o4;
}

// ---------------- host launch --------------------------------------------------
extern "C" void kernel_launch(void* const* d_in, const int* in_sizes, int n_in,
                              void* d_out, int out_size)
{
    const float* x   = (const float*)d_in[0];
    const float* Wq  = (const float*)d_in[1];
    const float* bq  = (const float*)d_in[2];
    const float* Wk  = (const float*)d_in[3];
    const float* bk  = (const float*)d_in[4];
    const float* Wv  = (const float*)d_in[5];
    const float* bv  = (const float*)d_in[6];
    const float* Wo  = (const float*)d_in[7];
    const float* bo  = (const float*)d_in[8];
    const float* W1  = (const float*)d_in[9];
    const float* b1  = (const float*)d_in[10];
    const float* W2  = (const float*)d_in[11];
    const float* b2  = (const float*)d_in[12];
    const float* g1  = (const float*)d_in[13];
    const float* be1 = (const float*)d_in[14];
    const float* g2  = (const float*)d_in[15];
    const float* be2 = (const float*)d_in[16];
    float* out = (float*)d_out;

    float *Qp, *Kp, *Vp, *AOp, *X1p, *FFHp, *WTp;
    cudaGetSymbolAddress((void**)&Qp,   g_Q);
    cudaGetSymbolAddress((void**)&Kp,   g_K);
    cudaGetSymbolAddress((void**)&Vp,   g_V);
    cudaGetSymbolAddress((void**)&AOp,  g_AO);
    cudaGetSymbolAddress((void**)&X1p,  g_X1);
    cudaGetSymbolAddress((void**)&FFHp, g_FFH);
    cudaGetSymbolAddress((void**)&WTp,  g_WT);

    const float* Wor = WTp + 3 * WSEG1;
    const float* W1r = WTp + 4 * WSEG1;
    const float* W2r = WTp + 4 * WSEG1 + WSEG2;

    cudaFuncSetAttribute(attn_tc, cudaFuncAttributeMaxDynamicSharedMemorySize, ATT_SMEM);
    cudaFuncSetAttribute(gemm_tc, cudaFuncAttributeMaxDynamicSharedMemorySize, GEMM_SMEM);
    cudaFuncSetAttribute(qkv_tc,  cudaFuncAttributeMaxDynamicSharedMemorySize, GEMM_SMEM);

    const dim3 t256(256), t128(128);
    const dim3 gQKV (DMODEL / TBN, ROWS / TBM, 3); // (4, 64, 3)
    const dim3 gProj(DMODEL / TBN, ROWS / TBM);    // (4, 64)
    const dim3 gFF1 (DFF    / TBN, ROWS / TBM);    // (16, 64)

    // round all weights to tf32 (rna) in one pass
    const int wtotal4 = (4 * WSEG1 + 2 * WSEG2) / 4;    // 786432 float4s
    wround<<<wtotal4 / 256, t256>>>(Wq, Wk, Wv, Wo, W1, W2, WTp);

    // QKV projections (fused launch, rounded weights)
    qkv_tc<<<gQKV, t256, GEMM_SMEM>>>(x, WTp, bq, bk, bv, Qp, Kp, Vp);

    // attention
    attn_tc<<<dim3(SEQ / QTILE, BATCH * NHEADS), t128, ATT_SMEM>>>(Qp, Kp, Vp, AOp);

    // output projection + LN1
    gemm_tc<<<gProj, t256, GEMM_SMEM>>>(AOp, Wor, bo, Qp, DMODEL, DMODEL, 0);
    add_ln_kernel<<<ROWS, 128>>>(x, Qp, g1, be1, X1p);

    // FFN
    gemm_tc<<<gFF1,  t256, GEMM_SMEM>>>(X1p,  W1r, b1, FFHp, DFF,    DMODEL, 1);
    gemm_tc<<<gProj, t256, GEMM_SMEM>>>(FFHp, W2r, b2, Kp,   DMODEL, DFF,    0);

    // LN2 -> final output
    add_ln_kernel<<<ROWS, 128>>>(X1p, Kp, g2, be2, out);
}

// round 15
// speedup vs baseline: 1.7273x; 1.6450x over previous
#include <cuda_runtime.h>
#include <cuda_fp16.h>
#include <math.h>
#include <stdint.h>

#define BATCH   2
#define SEQ     4096
#define DMODEL  512
#define NHEADS  8
#define DK      64
#define DFF     2048
#define ROWS    (BATCH * SEQ)   // 8192
#define EPS     1e-5f
#define WSEG1 (DMODEL * DMODEL)          // 262144
#define WSEG2 (DMODEL * DFF)             // 1048576

// ---------------- scratch (static device globals; no allocs allowed) ----------
__device__ __half g_Qh [ROWS * DMODEL];     // Q proj, pre-scaled, half
__device__ __half g_Kh [ROWS * DMODEL];     // K proj, half [seq][d]
__device__ __half g_Vt [ROWS * DMODEL];     // V proj, half, [bh][d][seq]
__device__ __half g_AOh[ROWS * DMODEL];     // attn out, half
__device__ __half g_xh [ROWS * DMODEL];     // input x, half
__device__ __half g_X1h[ROWS * DMODEL];     // post-LN1, half
__device__ __half g_FFHh[ROWS * DFF];       // FFN hidden, half
__device__ float  g_X1 [ROWS * DMODEL];     // post-LN1, fp32 (residual)
__device__ float  g_tmp[ROWS * DMODEL];     // fp32 GEMM outputs
__device__ __half g_Wh [4 * WSEG1 + 2 * WSEG2];  // weights, half, [N][K] layout

// ---------------- helpers -------------------------------------------------------
__device__ __forceinline__ float fex2(float x) {
    float y;
    asm("ex2.approx.f32 %0, %1;" : "=f"(y) : "f"(x));
    return y;
}

__device__ __forceinline__ void mma_f16(float* c,
                                        unsigned a0, unsigned a1, unsigned a2, unsigned a3,
                                        unsigned b0, unsigned b1)
{
    asm volatile(
        "mma.sync.aligned.m16n8k16.row.col.f32.f16.f16.f32 "
        "{%0,%1,%2,%3}, {%4,%5,%6,%7}, {%8,%9}, {%0,%1,%2,%3};"
        : "+f"(c[0]), "+f"(c[1]), "+f"(c[2]), "+f"(c[3])
        : "r"(a0), "r"(a1), "r"(a2), "r"(a3), "r"(b0), "r"(b1));
}

__device__ __forceinline__ void cp_async16(unsigned int smem_addr, const void* gptr) {
    asm volatile("cp.async.cg.shared.global [%0], [%1], 16;"
                 :: "r"(smem_addr), "l"(gptr));
}
#define CP_COMMIT() asm volatile("cp.async.commit_group;")
#define CP_WAIT0()  asm volatile("cp.async.wait_group 0;")

// ---------------- weight prep: out[N][K] = half(in[K][N])^T --------------------
__global__ void __launch_bounds__(256)
wprep_h(const float* __restrict__ in, __half* __restrict__ out, int K, int N)
{
    __shared__ float t[32][33];
    const int tx = threadIdx.x & 31, ty = threadIdx.x >> 5;  // (32, 8)
    const int n0 = blockIdx.x * 32, k0 = blockIdx.y * 32;
    #pragma unroll
    for (int i = 0; i < 4; i++)
        t[ty + 8 * i][tx] = in[(size_t)(k0 + ty + 8 * i) * N + n0 + tx];
    __syncthreads();
    #pragma unroll
    for (int i = 0; i < 4; i++)
        out[(size_t)(n0 + ty + 8 * i) * K + k0 + tx] = __float2half_rn(t[tx][ty + 8 * i]);
}

// ---------------- x -> half -----------------------------------------------------
__global__ void __launch_bounds__(256)
xconv(const float* __restrict__ in, __half* __restrict__ out)
{
    size_t i = (size_t)blockIdx.x * 256 + threadIdx.x;   // float4 index
    float4 v = reinterpret_cast<const float4*>(in)[i];
    *reinterpret_cast<__half2*>(out + i * 4)     = __floats2half2_rn(v.x, v.y);
    *reinterpret_cast<__half2*>(out + i * 4 + 2) = __floats2half2_rn(v.z, v.w);
}

// ---------------- fp16 GEMM mainloop: acc = A[M,K] @ Bt[N,K]^T ------------------
// block tile 128x128x64, 256 threads, warps 2(m) x 4(n), warp tile 64x32
#define TBM 128
#define TBN 128
#define TBKH 64
#define STRH 72
#define STGB ((TBM * STRH + TBN * STRH) * 2)     // 36864 bytes per stage
#define GEMM_SMEM (2 * STGB)                     // 73728 -> 2 CTAs/SM

__device__ __forceinline__ void gemm_main(
    const __half* __restrict__ A, const __half* __restrict__ Bt,
    int K, int row0, int col0, float acc[4][4][4])
{
    extern __shared__ __half hsm[];

    const int tid  = threadIdx.x;
    const int warp = tid >> 5, lane = tid & 31;
    const int wm = warp >> 2;          // 0..1
    const int wn = warp & 3;           // 0..3
    const int r    = lane >> 2;        // 0..7
    const int cg   = lane & 3;         // 0..3

    // per-thread chunks: each operand tile = 128 rows x 64 halves = 1024 16B chunks, 4/thread
    int tRow[4], tCh[4];
    unsigned int sOff[4];
    #pragma unroll
    for (int i = 0; i < 4; i++) {
        int c = tid + i * 256;
        tRow[i] = c >> 3;
        tCh[i]  = c & 7;
        sOff[i] = (unsigned int)(tRow[i] * STRH * 2 + tCh[i] * 16);
    }
    const unsigned int smemBase = (unsigned int)__cvta_generic_to_shared(hsm);

    auto issue = [&](int stg, int k0) {
        unsigned int sb = smemBase + (unsigned int)stg * STGB;
        #pragma unroll
        for (int i = 0; i < 4; i++) {
            cp_async16(sb + sOff[i],
                       A + (size_t)(row0 + tRow[i]) * K + k0 + tCh[i] * 8);
            cp_async16(sb + (unsigned int)(TBM * STRH * 2) + sOff[i],
                       Bt + (size_t)(col0 + tRow[i]) * K + k0 + tCh[i] * 8);
        }
        CP_COMMIT();
    };

    const int NT = K / TBKH;
    issue(0, 0);

    for (int kt = 0; kt < NT; kt++) {
        const int cur = kt & 1;
        CP_WAIT0();
        __syncthreads();

        if (kt + 1 < NT) issue(cur ^ 1, (kt + 1) * TBKH);

        const __half* As_ = hsm + cur * (STGB / 2);
        const __half* Bs_ = As_ + TBM * STRH;

        #pragma unroll
        for (int ks = 0; ks < 4; ks++) {
            const int kk = ks * 16;
            unsigned a[4][4];
            #pragma unroll
            for (int mi = 0; mi < 4; mi++) {
                int mb = wm * 64 + mi * 16;
                a[mi][0] = *reinterpret_cast<const unsigned*>(&As_[(mb + r    ) * STRH + kk + 2 * cg    ]);
                a[mi][1] = *reinterpret_cast<const unsigned*>(&As_[(mb + r + 8) * STRH + kk + 2 * cg    ]);
                a[mi][2] = *reinterpret_cast<const unsigned*>(&As_[(mb + r    ) * STRH + kk + 2 * cg + 8]);
                a[mi][3] = *reinterpret_cast<const unsigned*>(&As_[(mb + r + 8) * STRH + kk + 2 * cg + 8]);
            }
            #pragma unroll
            for (int ni = 0; ni < 4; ni++) {
                int nb = wn * 32 + ni * 8;
                unsigned b0 = *reinterpret_cast<const unsigned*>(&Bs_[(nb + r) * STRH + kk + 2 * cg    ]);
                unsigned b1 = *reinterpret_cast<const unsigned*>(&Bs_[(nb + r) * STRH + kk + 2 * cg + 8]);
                #pragma unroll
                for (int mi = 0; mi < 4; mi++)
                    mma_f16(acc[mi][ni], a[mi][0], a[mi][1], a[mi][2], a[mi][3], b0, b1);
            }
        }
    }
}

// fp32-output GEMM (Wo proj, FFN2)
__global__ void __launch_bounds__(256, 2)
gemm_f32(const __half* __restrict__ A, const __half* __restrict__ Bt,
         const float* __restrict__ bias, float* __restrict__ C, int N, int K)
{
    const int row0 = blockIdx.y * TBM, col0 = blockIdx.x * TBN;
    float acc[4][4][4] = {};
    gemm_main(A, Bt, K, row0, col0, acc);

    const int tid = threadIdx.x, warp = tid >> 5, lane = tid & 31;
    const int wm = warp >> 2, wn = warp & 3, r = lane >> 2, cg = lane & 3;
    #pragma unroll
    for (int mi = 0; mi < 4; mi++) {
        int mb = row0 + wm * 64 + mi * 16;
        #pragma unroll
        for (int ni = 0; ni < 4; ni++) {
            int col = col0 + wn * 32 + ni * 8 + 2 * cg;
            float bs0 = bias[col], bs1 = bias[col + 1];
            #pragma unroll
            for (int hf = 0; hf < 2; hf++) {
                int row = mb + r + hf * 8;
                *reinterpret_cast<float2*>(&C[(size_t)row * N + col]) =
                    make_float2(acc[mi][ni][2 * hf] + bs0, acc[mi][ni][2 * hf + 1] + bs1);
            }
        }
    }
}

// half-output + relu GEMM (FFN1)
__global__ void __launch_bounds__(256, 2)
gemm_h_relu(const __half* __restrict__ A, const __half* __restrict__ Bt,
            const float* __restrict__ bias, __half* __restrict__ Ch, int N, int K)
{
    const int row0 = blockIdx.y * TBM, col0 = blockIdx.x * TBN;
    float acc[4][4][4] = {};
    gemm_main(A, Bt, K, row0, col0, acc);

    const int tid = threadIdx.x, warp = tid >> 5, lane = tid & 31;
    const int wm = warp >> 2, wn = warp & 3, r = lane >> 2, cg = lane & 3;
    #pragma unroll
    for (int mi = 0; mi < 4; mi++) {
        int mb = row0 + wm * 64 + mi * 16;
        #pragma unroll
        for (int ni = 0; ni < 4; ni++) {
            int col = col0 + wn * 32 + ni * 8 + 2 * cg;
            float bs0 = bias[col], bs1 = bias[col + 1];
            #pragma unroll
            for (int hf = 0; hf < 2; hf++) {
                int row = mb + r + hf * 8;
                float v0 = fmaxf(acc[mi][ni][2 * hf]     + bs0, 0.0f);
                float v1 = fmaxf(acc[mi][ni][2 * hf + 1] + bs1, 0.0f);
                *reinterpret_cast<__half2*>(&Ch[(size_t)row * N + col]) = __floats2half2_rn(v0, v1);
            }
        }
    }
}

// fused QKV: z=0 -> Qh (scaled), z=1 -> Kh, z=2 -> Vt (transposed [bh][d][seq])
#define QSCALE 0.18033688011f   // 0.125 * log2(e)
__global__ void __launch_bounds__(256, 2)
qkv_h(const __half* __restrict__ xh, const __half* __restrict__ Wh,
      const float* __restrict__ bq, const float* __restrict__ bk, const float* __restrict__ bv,
      __half* __restrict__ Qh, __half* __restrict__ Kh, __half* __restrict__ Vt)
{
    const int z = blockIdx.z;
    const __half* Bt = Wh + (size_t)z * WSEG1;
    const float* bias = (z == 0) ? bq : (z == 1) ? bk : bv;
    const int row0 = blockIdx.y * TBM, col0 = blockIdx.x * TBN;

    float acc[4][4][4] = {};
    gemm_main(xh, Bt, DMODEL, row0, col0, acc);

    const int tid = threadIdx.x, warp = tid >> 5, lane = tid & 31;
    const int wm = warp >> 2, wn = warp & 3, r = lane >> 2, cg = lane & 3;
    #pragma unroll
    for (int mi = 0; mi < 4; mi++) {
        int mb = row0 + wm * 64 + mi * 16;
        #pragma unroll
        for (int ni = 0; ni < 4; ni++) {
            int col = col0 + wn * 32 + ni * 8 + 2 * cg;
            float bs0 = bias[col], bs1 = bias[col + 1];
            #pragma unroll
            for (int hf = 0; hf < 2; hf++) {
                int row = mb + r + hf * 8;
                float v0 = acc[mi][ni][2 * hf]     + bs0;
                float v1 = acc[mi][ni][2 * hf + 1] + bs1;
                if (z == 0) {
                    *reinterpret_cast<__half2*>(&Qh[(size_t)row * DMODEL + col]) =
                        __floats2half2_rn(v0 * QSCALE, v1 * QSCALE);
                } else if (z == 1) {
                    *reinterpret_cast<__half2*>(&Kh[(size_t)row * DMODEL + col]) =
                        __floats2half2_rn(v0, v1);
                } else {
                    int bh  = (row >> 12) * 8 + (col >> 6);
                    int d   = col & 63;
                    int seq = row & 4095;
                    size_t bbase = (size_t)bh * (64 * 4096) + (size_t)d * 4096 + seq;
                    Vt[bbase]        = __float2half_rn(v0);
                    Vt[bbase + 4096] = __float2half_rn(v1);
                }
            }
        }
    }
}

// ---------------- flash attention, fp16 mma -------------------------------------
#define QTILE 128
#define KTILE 64
#define ASTMH 72
#define ATT_SMEM ((QTILE * ASTMH + KTILE * ASTMH + KTILE * ASTMH + QTILE * ASTMH) * 2)

__global__ void __launch_bounds__(128)
attn_h(const __half* __restrict__ Q, const __half* __restrict__ K,
       const __half* __restrict__ Vt, __half* __restrict__ O)
{
    extern __shared__ __half ash[];
    __half* Qs  = ash;                       // [128][72]
    __half* Ks  = Qs + QTILE * ASTMH;        // [64][72]  ([seq][d])
    __half* Vts = Ks + KTILE * ASTMH;        // [64][72]  ([d][seq])
    __half* Ps  = Vts + KTILE * ASTMH;       // [128][72] ([qrow][seq])

    const int tid  = threadIdx.x;
    const int warp = tid >> 5, lane = tid & 31;
    const int r    = lane >> 2;
    const int cg   = lane & 3;
    const int wb   = warp * 32;

    const int qt = blockIdx.x;
    const int bh = blockIdx.y;
    const int b  = bh >> 3, h = bh & 7;
    const int base = b * SEQ;
    const int q0   = base + qt * QTILE;
    const int colh = h * DK;
    const __half* VtB = Vt + (size_t)bh * (64 * 4096);

    int kvRow[4], kvCh[4];
    unsigned int ksAddr[4], vsAddr[4];
    #pragma unroll
    for (int i = 0; i < 4; i++) {
        int c = tid + i * 128;
        kvRow[i] = c >> 3;
        kvCh[i]  = c & 7;
        unsigned off = (unsigned)(kvRow[i] * ASTMH * 2 + kvCh[i] * 16);
        ksAddr[i] = (unsigned int)__cvta_generic_to_shared(Ks)  + off;
        vsAddr[i] = (unsigned int)__cvta_generic_to_shared(Vts) + off;
    }

    // prologue: K(0) + Q (single cp.async group)
    #pragma unroll
    for (int i = 0; i < 4; i++)
        cp_async16(ksAddr[i], K + (size_t)(base + kvRow[i]) * DMODEL + colh + kvCh[i] * 8);
    {
        unsigned int qsb = (unsigned int)__cvta_generic_to_shared(Qs);
        #pragma unroll
        for (int i = 0; i < 8; i++) {
            int c = tid + i * 128;
            int row = c >> 3, ch = c & 7;
            cp_async16(qsb + (unsigned)(row * ASTMH * 2 + ch * 16),
                       Q + (size_t)(q0 + row) * DMODEL + colh + ch * 8);
        }
    }
    CP_COMMIT();

    float o[2][8][4] = {};
    float rmax[2][2], rsum[2][2];
    #pragma unroll
    for (int mf = 0; mf < 2; mf++)
        #pragma unroll
        for (int z = 0; z < 2; z++) { rmax[mf][z] = -1e30f; rsum[mf][z] = 0.0f; }

    for (int j0 = 0; j0 < SEQ; j0 += KTILE) {
        const int kr = base + j0;

        CP_WAIT0();
        __syncthreads();                 // Ks(j) (+Q first iter) ready; Vts free

        #pragma unroll
        for (int i = 0; i < 4; i++)
            cp_async16(vsAddr[i], VtB + (size_t)kvRow[i] * 4096 + j0 + kvCh[i] * 8);
        CP_COMMIT();

        // S = Q @ K^T : per warp m32 x n64 x k64 (4 x k16)
        float s[2][8][4] = {};
        #pragma unroll
        for (int ks = 0; ks < 4; ks++) {
            const int kk = ks * 16;
            unsigned a[2][4];
            #pragma unroll
            for (int mf = 0; mf < 2; mf++) {
                int mb = wb + mf * 16;
                a[mf][0] = *reinterpret_cast<const unsigned*>(&Qs[(mb + r    ) * ASTMH + kk + 2 * cg    ]);
                a[mf][1] = *reinterpret_cast<const unsigned*>(&Qs[(mb + r + 8) * ASTMH + kk + 2 * cg    ]);
                a[mf][2] = *reinterpret_cast<const unsigned*>(&Qs[(mb + r    ) * ASTMH + kk + 2 * cg + 8]);
                a[mf][3] = *reinterpret_cast<const unsigned*>(&Qs[(mb + r + 8) * ASTMH + kk + 2 * cg + 8]);
            }
            #pragma unroll
            for (int ni = 0; ni < 8; ni++) {
                unsigned b0 = *reinterpret_cast<const unsigned*>(&Ks[(ni * 8 + r) * ASTMH + kk + 2 * cg    ]);
                unsigned b1 = *reinterpret_cast<const unsigned*>(&Ks[(ni * 8 + r) * ASTMH + kk + 2 * cg + 8]);
                mma_f16(s[0][ni], a[0][0], a[0][1], a[0][2], a[0][3], b0, b1);
                mma_f16(s[1][ni], a[1][0], a[1][1], a[1][2], a[1][3], b0, b1);
            }
        }

        // online softmax (log2 domain; overlaps V(j) DMA)
        #pragma unroll
        for (int mf = 0; mf < 2; mf++) {
            #pragma unroll
            for (int z = 0; z < 2; z++) {
                float mx = -1e30f;
                #pragma unroll
                for (int ni = 0; ni < 8; ni++)
                    mx = fmaxf(mx, fmaxf(s[mf][ni][2 * z], s[mf][ni][2 * z + 1]));
                mx = fmaxf(mx, __shfl_xor_sync(0xffffffffu, mx, 1));
                mx = fmaxf(mx, __shfl_xor_sync(0xffffffffu, mx, 2));
                float nm   = fmaxf(rmax[mf][z], mx);
                float corr = fex2(rmax[mf][z] - nm);
                rmax[mf][z] = nm;
                float ps = 0.0f;
                #pragma unroll
                for (int ni = 0; ni < 8; ni++) {
                    float e0 = fex2(s[mf][ni][2 * z]     - nm);
                    float e1 = fex2(s[mf][ni][2 * z + 1] - nm);
                    s[mf][ni][2 * z] = e0; s[mf][ni][2 * z + 1] = e1;
                    ps += e0 + e1;
                }
                ps += __shfl_xor_sync(0xffffffffu, ps, 1);
                ps += __shfl_xor_sync(0xffffffffu, ps, 2);
                rsum[mf][z] = rsum[mf][z] * corr + ps;
                #pragma unroll
                for (int ni = 0; ni < 8; ni++) {
                    o[mf][ni][2 * z]     *= corr;
                    o[mf][ni][2 * z + 1] *= corr;
                }
            }
        }

        CP_WAIT0();
        __syncthreads();                 // Vts(j) ready; Ks free

        // write P (half2)
        #pragma unroll
        for (int mf = 0; mf < 2; mf++) {
            #pragma unroll
            for (int ni = 0; ni < 8; ni++) {
                int col = ni * 8 + 2 * cg;
                #pragma unroll
                for (int z = 0; z < 2; z++) {
                    int row = wb + mf * 16 + r + z * 8;
                    *reinterpret_cast<__half2*>(&Ps[row * ASTMH + col]) =
                        __floats2half2_rn(s[mf][ni][2 * z], s[mf][ni][2 * z + 1]);
                }
            }
        }
        __syncwarp();

        if (j0 + KTILE < SEQ) {
            #pragma unroll
            for (int i = 0; i < 4; i++)
                cp_async16(ksAddr[i], K + (size_t)(kr + KTILE + kvRow[i]) * DMODEL + colh + kvCh[i] * 8);
            CP_COMMIT();
        }

        // O += P @ V : per warp m32 x n64(d) x k64(seq)
        #pragma unroll
        for (int ks = 0; ks < 4; ks++) {
            const int kk = ks * 16;
            unsigned a[2][4];
            #pragma unroll
            for (int mf = 0; mf < 2; mf++) {
                int mb = wb + mf * 16;
                a[mf][0] = *reinterpret_cast<const unsigned*>(&Ps[(mb + r    ) * ASTMH + kk + 2 * cg    ]);
                a[mf][1] = *reinterpret_cast<const unsigned*>(&Ps[(mb + r + 8) * ASTMH + kk + 2 * cg    ]);
                a[mf][2] = *reinterpret_cast<const unsigned*>(&Ps[(mb + r    ) * ASTMH + kk + 2 * cg + 8]);
                a[mf][3] = *reinterpret_cast<const unsigned*>(&Ps[(mb + r + 8) * ASTMH + kk + 2 * cg + 8]);
            }
            #pragma unroll
            for (int ni = 0; ni < 8; ni++) {
                unsigned b0 = *reinterpret_cast<const unsigned*>(&Vts[(ni * 8 + r) * ASTMH + kk + 2 * cg    ]);
                unsigned b1 = *reinterpret_cast<const unsigned*>(&Vts[(ni * 8 + r) * ASTMH + kk + 2 * cg + 8]);
                mma_f16(o[0][ni], a[0][0], a[0][1], a[0][2], a[0][3], b0, b1);
                mma_f16(o[1][ni], a[1][0], a[1][1], a[1][2], a[1][3], b0, b1);
            }
        }
    }

    // epilogue: normalize, store half
    #pragma unroll
    for (int mf = 0; mf < 2; mf++) {
        #pragma unroll
        for (int z = 0; z < 2; z++) {
            float inv = 1.0f / rsum[mf][z];
            int row = q0 + wb + mf * 16 + r + z * 8;
            #pragma unroll
            for (int ni = 0; ni < 8; ni++) {
                int col = colh + ni * 8 + 2 * cg;
                *reinterpret_cast<__half2*>(&O[(size_t)row * DMODEL + col]) =
                    __floats2half2_rn(o[mf][ni][2 * z] * inv, o[mf][ni][2 * z + 1] * inv);
            }
        }
    }
}

// ---------------- residual add + layernorm (reference form: /(std+eps)) -------
__global__ void __launch_bounds__(128)
add_ln_kernel(const float* __restrict__ A, const float* __restrict__ Bv,
              const float* __restrict__ gamma, const float* __restrict__ beta,
              float* __restrict__ out, __half* __restrict__ outh)
{
    const int row = blockIdx.x;
    const int tid = threadIdx.x;
    __shared__ float red[4];

    const float4 a4 = reinterpret_cast<const float4*>(A  + (size_t)row * DMODEL)[tid];
    const float4 b4 = reinterpret_cast<const float4*>(Bv + (size_t)row * DMODEL)[tid];
    float x0 = a4.x + b4.x, x1 = a4.y + b4.y, x2 = a4.z + b4.z, x3 = a4.w + b4.w;

    float s = x0 + x1 + x2 + x3;
    #pragma unroll
    for (int off = 16; off; off >>= 1) s += __shfl_xor_sync(0xffffffffu, s, off);
    if ((tid & 31) == 0) red[tid >> 5] = s;
    __syncthreads();
    s = red[0] + red[1] + red[2] + red[3];
    const float mean = s * (1.0f / DMODEL);

    float d0 = x0 - mean, d1 = x1 - mean, d2 = x2 - mean, d3 = x3 - mean;
    float v = d0 * d0 + d1 * d1 + d2 * d2 + d3 * d3;
    #pragma unroll
    for (int off = 16; off; off >>= 1) v += __shfl_xor_sync(0xffffffffu, v, off);
    __syncthreads();
    if ((tid & 31) == 0) red[tid >> 5] = v;
    __syncthreads();
    v = (red[0] + red[1] + red[2] + red[3]) * (1.0f / DMODEL);

    const float inv = 1.0f / (sqrtf(v) + EPS);
    const float4 g4  = reinterpret_cast<const float4*>(gamma)[tid];
    const float4 be4 = reinterpret_cast<const float4*>(beta )[tid];
    float4 o4;
    o4.x = d0 * inv * g4.x + be4.x;
    o4.y = d1 * inv * g4.y + be4.y;
    o4.z = d2 * inv * g4.z + be4.z;
    o4.w = d3 * inv * g4.w + be4.w;
    reinterpret_cast<float4*>(out + (size_t)row * DMODEL)[tid] = o4;
    if (outh != 0) {
        *reinterpret_cast<__half2*>(outh + (size_t)row * DMODEL + tid * 4)     = __floats2half2_rn(o4.x, o4.y);
        *reinterpret_cast<__half2*>(outh + (size_t)row * DMODEL + tid * 4 + 2) = __floats2half2_rn(o4.z, o4.w);
    }
}

// ---------------- host launch --------------------------------------------------
extern "C" void kernel_launch(void* const* d_in, const int* in_sizes, int n_in,
                              void* d_out, int out_size)
{
    const float* x   = (const float*)d_in[0];
    const float* Wq  = (const float*)d_in[1];
    const float* bq  = (const float*)d_in[2];
    const float* Wk  = (const float*)d_in[3];
    const float* bk  = (const float*)d_in[4];
    const float* Wv  = (const float*)d_in[5];
    const float* bv  = (const float*)d_in[6];
    const float* Wo  = (const float*)d_in[7];
    const float* bo  = (const float*)d_in[8];
    const float* W1  = (const float*)d_in[9];
    const float* b1  = (const float*)d_in[10];
    const float* W2  = (const float*)d_in[11];
    const float* b2  = (const float*)d_in[12];
    const float* g1  = (const float*)d_in[13];
    const float* be1 = (const float*)d_in[14];
    const float* g2  = (const float*)d_in[15];
    const float* be2 = (const float*)d_in[16];
    float* out = (float*)d_out;

    __half *Qh, *Kh, *Vt, *AOh, *xh, *X1h, *FFHh, *Wh;
    float *X1, *tmp;
    cudaGetSymbolAddress((void**)&Qh,   g_Qh);
    cudaGetSymbolAddress((void**)&Kh,   g_Kh);
    cudaGetSymbolAddress((void**)&Vt,   g_Vt);
    cudaGetSymbolAddress((void**)&AOh,  g_AOh);
    cudaGetSymbolAddress((void**)&xh,   g_xh);
    cudaGetSymbolAddress((void**)&X1h,  g_X1h);
    cudaGetSymbolAddress((void**)&FFHh, g_FFHh);
    cudaGetSymbolAddress((void**)&Wh,   g_Wh);
    cudaGetSymbolAddress((void**)&X1,   g_X1);
    cudaGetSymbolAddress((void**)&tmp,  g_tmp);

    __half* Woh = Wh + 3 * WSEG1;
    __half* W1h = Wh + 4 * WSEG1;               // [2048][512]
    __half* W2h = Wh + 4 * WSEG1 + WSEG2;       // [512][2048]

    cudaFuncSetAttribute(attn_h,      cudaFuncAttributeMaxDynamicSharedMemorySize, ATT_SMEM);
    cudaFuncSetAttribute(gemm_f32,    cudaFuncAttributeMaxDynamicSharedMemorySize, GEMM_SMEM);
    cudaFuncSetAttribute(gemm_h_relu, cudaFuncAttributeMaxDynamicSharedMemorySize, GEMM_SMEM);
    cudaFuncSetAttribute(qkv_h,       cudaFuncAttributeMaxDynamicSharedMemorySize, GEMM_SMEM);

    const dim3 t256(256), t128(128);

    // weight prep: half + transpose to [N][K]
    wprep_h<<<dim3(DMODEL / 32, DMODEL / 32), t256>>>(Wq, Wh,             DMODEL, DMODEL);
    wprep_h<<<dim3(DMODEL / 32, DMODEL / 32), t256>>>(Wk, Wh + 1 * WSEG1, DMODEL, DMODEL);
    wprep_h<<<dim3(DMODEL / 32, DMODEL / 32), t256>>>(Wv, Wh + 2 * WSEG1, DMODEL, DMODEL);
    wprep_h<<<dim3(DMODEL / 32, DMODEL / 32), t256>>>(Wo, Woh,            DMODEL, DMODEL);
    wprep_h<<<dim3(DFF / 32,    DMODEL / 32), t256>>>(W1, W1h,            DMODEL, DFF);
    wprep_h<<<dim3(DMODEL / 32, DFF / 32),    t256>>>(W2, W2h,            DFF,    DMODEL);

    // input -> half
    xconv<<<(ROWS * DMODEL / 4) / 256, t256>>>(x, xh);

    // QKV projections (fused fp16 launch)
    qkv_h<<<dim3(DMODEL / TBN, ROWS / TBM, 3), t256, GEMM_SMEM>>>(
        xh, Wh, bq, bk, bv, Qh, Kh, Vt);

    // attention
    attn_h<<<dim3(SEQ / QTILE, BATCH * NHEADS), t128, ATT_SMEM>>>(Qh, Kh, Vt, AOh);

    // output projection + LN1 (dual output: fp32 residual + half for FFN1)
    gemm_f32<<<dim3(DMODEL / TBN, ROWS / TBM), t256, GEMM_SMEM>>>(AOh, Woh, bo, tmp, DMODEL, DMODEL);
    add_ln_kernel<<<ROWS, 128>>>(x, tmp, g1, be1, X1, X1h);

    // FFN
    gemm_h_relu<<<dim3(DFF / TBN, ROWS / TBM), t256, GEMM_SMEM>>>(X1h, W1h, b1, FFHh, DFF, DMODEL);
    gemm_f32<<<dim3(DMODEL / TBN, ROWS / TBM), t256, GEMM_SMEM>>>(FFHh, W2h, b2, tmp, DMODEL, DFF);

    // LN2 -> final output
    add_ln_kernel<<<ROWS, 128>>>(X1, tmp, g2, be2, out, (__half*)0);
}

// round 16
// speedup vs baseline: 1.8048x; 1.0449x over previous
#include <cuda_runtime.h>
#include <cuda_fp16.h>
#include <math.h>
#include <stdint.h>

#define BATCH   2
#define SEQ     4096
#define DMODEL  512
#define NHEADS  8
#define DK      64
#define DFF     2048
#define ROWS    (BATCH * SEQ)   // 8192
#define EPS     1e-5f
#define WSEG1 (DMODEL * DMODEL)          // 262144
#define WSEG2 (DMODEL * DFF)             // 1048576

// ---------------- scratch (static device globals; no allocs allowed) ----------
__device__ __half g_Qh [ROWS * DMODEL];     // Q proj, pre-scaled, half
__device__ __half g_Kh [ROWS * DMODEL];     // K proj, half [seq][d]
__device__ __half g_Vt [ROWS * DMODEL];     // V proj, half, [bh][d][seq]
__device__ __half g_AOh[ROWS * DMODEL];     // attn out, half
__device__ __half g_xh [ROWS * DMODEL];     // input x, half
__device__ __half g_X1h[ROWS * DMODEL];     // post-LN1, half
__device__ __half g_FFHh[ROWS * DFF];       // FFN hidden, half
__device__ float  g_X1 [ROWS * DMODEL];     // post-LN1, fp32 (residual)
__device__ float  g_tmp[ROWS * DMODEL];     // fp32 GEMM outputs
__device__ __half g_Wh [4 * WSEG1 + 2 * WSEG2];  // weights, half, [N][K] layout

// ---------------- helpers -------------------------------------------------------
__device__ __forceinline__ float fex2(float x) {
    float y;
    asm("ex2.approx.f32 %0, %1;" : "=f"(y) : "f"(x));
    return y;
}

__device__ __forceinline__ void mma_f16(float* c,
                                        unsigned a0, unsigned a1, unsigned a2, unsigned a3,
                                        unsigned b0, unsigned b1)
{
    asm volatile(
        "mma.sync.aligned.m16n8k16.row.col.f32.f16.f16.f32 "
        "{%0,%1,%2,%3}, {%4,%5,%6,%7}, {%8,%9}, {%0,%1,%2,%3};"
        : "+f"(c[0]), "+f"(c[1]), "+f"(c[2]), "+f"(c[3])
        : "r"(a0), "r"(a1), "r"(a2), "r"(a3), "r"(b0), "r"(b1));
}

__device__ __forceinline__ void ldsm_x4(unsigned& r0, unsigned& r1, unsigned& r2, unsigned& r3,
                                        unsigned int addr)
{
    asm volatile("ldmatrix.sync.aligned.m8n8.x4.shared.b16 {%0,%1,%2,%3}, [%4];"
                 : "=r"(r0), "=r"(r1), "=r"(r2), "=r"(r3) : "r"(addr));
}

__device__ __forceinline__ void cp_async16(unsigned int smem_addr, const void* gptr) {
    asm volatile("cp.async.cg.shared.global [%0], [%1], 16;"
                 :: "r"(smem_addr), "l"(gptr));
}
#define CP_COMMIT() asm volatile("cp.async.commit_group;")
#define CP_WAIT0()  asm volatile("cp.async.wait_group 0;")

// ---------------- weight prep: out[N][K] = half(in[K][N])^T --------------------
__global__ void __launch_bounds__(256)
wprep_h(const float* __restrict__ in, __half* __restrict__ out, int K, int N)
{
    __shared__ float t[32][33];
    const int tx = threadIdx.x & 31, ty = threadIdx.x >> 5;  // (32, 8)
    const int n0 = blockIdx.x * 32, k0 = blockIdx.y * 32;
    #pragma unroll
    for (int i = 0; i < 4; i++)
        t[ty + 8 * i][tx] = in[(size_t)(k0 + ty + 8 * i) * N + n0 + tx];
    __syncthreads();
    #pragma unroll
    for (int i = 0; i < 4; i++)
        out[(size_t)(n0 + ty + 8 * i) * K + k0 + tx] = __float2half_rn(t[tx][ty + 8 * i]);
}

// ---------------- x -> half -----------------------------------------------------
__global__ void __launch_bounds__(256)
xconv(const float* __restrict__ in, __half* __restrict__ out)
{
    size_t i = (size_t)blockIdx.x * 256 + threadIdx.x;   // float4 index
    float4 v = reinterpret_cast<const float4*>(in)[i];
    *reinterpret_cast<__half2*>(out + i * 4)     = __floats2half2_rn(v.x, v.y);
    *reinterpret_cast<__half2*>(out + i * 4 + 2) = __floats2half2_rn(v.z, v.w);
}

// ---------------- fp16 GEMM mainloop: acc = A[M,K] @ Bt[N,K]^T ------------------
// block tile 128x128x64, 256 threads, warps 2(m) x 4(n), warp tile 64x32
#define TBM 128
#define TBN 128
#define TBKH 64
#define STRH 72
#define STGB ((TBM * STRH + TBN * STRH) * 2)     // 36864 bytes per stage
#define GEMM_SMEM (2 * STGB)                     // 73728 -> 2 CTAs/SM

__device__ __forceinline__ void gemm_main(
    const __half* __restrict__ A, const __half* __restrict__ Bt,
    int K, int row0, int col0, float acc[4][4][4])
{
    extern __shared__ __half hsm[];

    const int tid  = threadIdx.x;
    const int warp = tid >> 5, lane = tid & 31;
    const int wm = warp >> 2;          // 0..1
    const int wn = warp & 3;           // 0..3
    const int lq = lane >> 3;          // 0..3 (ldmatrix quad)
    const int lr = lane & 7;           // 0..7 (ldmatrix row)

    // per-thread cp.async chunks: each operand tile = 128 rows x 64 halves = 1024 16B chunks, 4/thread
    int tRow[4], tCh[4];
    unsigned int sOff[4];
    #pragma unroll
    for (int i = 0; i < 4; i++) {
        int c = tid + i * 256;
        tRow[i] = c >> 3;
        tCh[i]  = c & 7;
        sOff[i] = (unsigned int)(tRow[i] * STRH * 2 + tCh[i] * 16);
    }
    const unsigned int smemBase = (unsigned int)__cvta_generic_to_shared(hsm);

    // ldmatrix lane-relative offsets (bytes within a stage)
    // A x4: matrices (m0-7,k0-7),(m8-15,k0-7),(m0-7,k8-15),(m8-15,k8-15)
    const unsigned int aOffL = (unsigned int)(((wm * 64 + lr + (lq & 1) * 8) * STRH + (lq >> 1) * 8) * 2);
    // B x4 over n-pair: (n0-7,k0-7),(n0-7,k8-15),(n8-15,k0-7),(n8-15,k8-15)
    const unsigned int bOffL = (unsigned int)(TBM * STRH * 2 +
                               ((wn * 32 + lr + (lq >> 1) * 8) * STRH + (lq & 1) * 8) * 2);

    auto issue = [&](int stg, int k0) {
        unsigned int sb = smemBase + (unsigned int)stg * STGB;
        #pragma unroll
        for (int i = 0; i < 4; i++) {
            cp_async16(sb + sOff[i],
                       A + (size_t)(row0 + tRow[i]) * K + k0 + tCh[i] * 8);
            cp_async16(sb + (unsigned int)(TBM * STRH * 2) + sOff[i],
                       Bt + (size_t)(col0 + tRow[i]) * K + k0 + tCh[i] * 8);
        }
        CP_COMMIT();
    };

    const int NT = K / TBKH;
    issue(0, 0);

    for (int kt = 0; kt < NT; kt++) {
        const int cur = kt & 1;
        CP_WAIT0();
        __syncthreads();

        if (kt + 1 < NT) issue(cur ^ 1, (kt + 1) * TBKH);

        const unsigned int stB = smemBase + (unsigned int)cur * STGB;
        const unsigned int aB = stB + aOffL;
        const unsigned int bB = stB + bOffL;

        #pragma unroll
        for (int ks = 0; ks < 4; ks++) {
            const unsigned int kb = (unsigned int)ks * 32;   // 16 halves
            unsigned a[4][4];
            #pragma unroll
            for (int mi = 0; mi < 4; mi++)
                ldsm_x4(a[mi][0], a[mi][1], a[mi][2], a[mi][3],
                        aB + (unsigned int)(mi * 16 * STRH * 2) + kb);
            #pragma unroll
            for (int p = 0; p < 2; p++) {
                unsigned b00, b01, b10, b11;
                ldsm_x4(b00, b01, b10, b11, bB + (unsigned int)(p * 16 * STRH * 2) + kb);
                #pragma unroll
                for (int mi = 0; mi < 4; mi++) {
                    mma_f16(acc[mi][2 * p],     a[mi][0], a[mi][1], a[mi][2], a[mi][3], b00, b01);
                    mma_f16(acc[mi][2 * p + 1], a[mi][0], a[mi][1], a[mi][2], a[mi][3], b10, b11);
                }
            }
        }
    }
}

// fp32-output GEMM (Wo proj, FFN2)
__global__ void __launch_bounds__(256, 2)
gemm_f32(const __half* __restrict__ A, const __half* __restrict__ Bt,
         const float* __restrict__ bias, float* __restrict__ C, int N, int K)
{
    const int row0 = blockIdx.y * TBM, col0 = blockIdx.x * TBN;
    float acc[4][4][4] = {};
    gemm_main(A, Bt, K, row0, col0, acc);

    const int tid = threadIdx.x, warp = tid >> 5, lane = tid & 31;
    const int wm = warp >> 2, wn = warp & 3, r = lane >> 2, cg = lane & 3;
    #pragma unroll
    for (int mi = 0; mi < 4; mi++) {
        int mb = row0 + wm * 64 + mi * 16;
        #pragma unroll
        for (int ni = 0; ni < 4; ni++) {
            int col = col0 + wn * 32 + ni * 8 + 2 * cg;
            float bs0 = bias[col], bs1 = bias[col + 1];
            #pragma unroll
            for (int hf = 0; hf < 2; hf++) {
                int row = mb + r + hf * 8;
                *reinterpret_cast<float2*>(&C[(size_t)row * N + col]) =
                    make_float2(acc[mi][ni][2 * hf] + bs0, acc[mi][ni][2 * hf + 1] + bs1);
            }
        }
    }
}

// half-output + relu GEMM (FFN1)
__global__ void __launch_bounds__(256, 2)
gemm_h_relu(const __half* __restrict__ A, const __half* __restrict__ Bt,
            const float* __restrict__ bias, __half* __restrict__ Ch, int N, int K)
{
    const int row0 = blockIdx.y * TBM, col0 = blockIdx.x * TBN;
    float acc[4][4][4] = {};
    gemm_main(A, Bt, K, row0, col0, acc);

    const int tid = threadIdx.x, warp = tid >> 5, lane = tid & 31;
    const int wm = warp >> 2, wn = warp & 3, r = lane >> 2, cg = lane & 3;
    #pragma unroll
    for (int mi = 0; mi < 4; mi++) {
        int mb = row0 + wm * 64 + mi * 16;
        #pragma unroll
        for (int ni = 0; ni < 4; ni++) {
            int col = col0 + wn * 32 + ni * 8 + 2 * cg;
            float bs0 = bias[col], bs1 = bias[col + 1];
            #pragma unroll
            for (int hf = 0; hf < 2; hf++) {
                int row = mb + r + hf * 8;
                float v0 = fmaxf(acc[mi][ni][2 * hf]     + bs0, 0.0f);
                float v1 = fmaxf(acc[mi][ni][2 * hf + 1] + bs1, 0.0f);
                *reinterpret_cast<__half2*>(&Ch[(size_t)row * N + col]) = __floats2half2_rn(v0, v1);
            }
        }
    }
}

// fused QKV: z=0 -> Qh (scaled), z=1 -> Kh, z=2 -> Vt (transposed [bh][d][seq])
#define QSCALE 0.18033688011f   // 0.125 * log2(e)
__global__ void __launch_bounds__(256, 2)
qkv_h(const __half* __restrict__ xh, const __half* __restrict__ Wh,
      const float* __restrict__ bq, const float* __restrict__ bk, const float* __restrict__ bv,
      __half* __restrict__ Qh, __half* __restrict__ Kh, __half* __restrict__ Vt)
{
    const int z = blockIdx.z;
    const __half* Bt = Wh + (size_t)z * WSEG1;
    const float* bias = (z == 0) ? bq : (z == 1) ? bk : bv;
    const int row0 = blockIdx.y * TBM, col0 = blockIdx.x * TBN;

    float acc[4][4][4] = {};
    gemm_main(xh, Bt, DMODEL, row0, col0, acc);

    const int tid = threadIdx.x, warp = tid >> 5, lane = tid & 31;
    const int wm = warp >> 2, wn = warp & 3, r = lane >> 2, cg = lane & 3;
    #pragma unroll
    for (int mi = 0; mi < 4; mi++) {
        int mb = row0 + wm * 64 + mi * 16;
        #pragma unroll
        for (int ni = 0; ni < 4; ni++) {
            int col = col0 + wn * 32 + ni * 8 + 2 * cg;
            float bs0 = bias[col], bs1 = bias[col + 1];
            #pragma unroll
            for (int hf = 0; hf < 2; hf++) {
                int row = mb + r + hf * 8;
                float v0 = acc[mi][ni][2 * hf]     + bs0;
                float v1 = acc[mi][ni][2 * hf + 1] + bs1;
                if (z == 0) {
                    *reinterpret_cast<__half2*>(&Qh[(size_t)row * DMODEL + col]) =
                        __floats2half2_rn(v0 * QSCALE, v1 * QSCALE);
                } else if (z == 1) {
                    *reinterpret_cast<__half2*>(&Kh[(size_t)row * DMODEL + col]) =
                        __floats2half2_rn(v0, v1);
                } else {
                    int bh  = (row >> 12) * 8 + (col >> 6);
                    int d   = col & 63;
                    int seq = row & 4095;
                    size_t bbase = (size_t)bh * (64 * 4096) + (size_t)d * 4096 + seq;
                    Vt[bbase]        = __float2half_rn(v0);
                    Vt[bbase + 4096] = __float2half_rn(v1);
                }
            }
        }
    }
}

// ---------------- flash attention, fp16 mma + ldmatrix --------------------------
#define QTILE 128
#define KTILE 64
#define ASTMH 72
#define ATT_SMEM ((QTILE * ASTMH + KTILE * ASTMH + KTILE * ASTMH + QTILE * ASTMH) * 2)

__global__ void __launch_bounds__(128)
attn_h(const __half* __restrict__ Q, const __half* __restrict__ K,
       const __half* __restrict__ Vt, __half* __restrict__ O)
{
    extern __shared__ __half ash[];
    __half* Qs  = ash;                       // [128][72]
    __half* Ks  = Qs + QTILE * ASTMH;        // [64][72]  ([seq][d])
    __half* Vts = Ks + KTILE * ASTMH;        // [64][72]  ([d][seq])
    __half* Ps  = Vts + KTILE * ASTMH;       // [128][72] ([qrow][seq])

    const int tid  = threadIdx.x;
    const int warp = tid >> 5, lane = tid & 31;
    const int r    = lane >> 2;
    const int cg   = lane & 3;
    const int lq   = lane >> 3;              // ldmatrix quad
    const int lr   = lane & 7;               // ldmatrix row
    const int wb   = warp * 32;

    const int qt = blockIdx.x;
    const int bh = blockIdx.y;
    const int b  = bh >> 3, h = bh & 7;
    const int base = b * SEQ;
    const int q0   = base + qt * QTILE;
    const int colh = h * DK;
    const __half* VtB = Vt + (size_t)bh * (64 * 4096);

    int kvRow[4], kvCh[4];
    unsigned int ksAddr[4], vsAddr[4];
    #pragma unroll
    for (int i = 0; i < 4; i++) {
        int c = tid + i * 128;
        kvRow[i] = c >> 3;
        kvCh[i]  = c & 7;
        unsigned off = (unsigned)(kvRow[i] * ASTMH * 2 + kvCh[i] * 16);
        ksAddr[i] = (unsigned int)__cvta_generic_to_shared(Ks)  + off;
        vsAddr[i] = (unsigned int)__cvta_generic_to_shared(Vts) + off;
    }

    // ldmatrix lane-relative base addresses
    const unsigned int aRel = (unsigned int)(((wb + lr + (lq & 1) * 8) * ASTMH + (lq >> 1) * 8) * 2);
    const unsigned int bRel = (unsigned int)(((lr + (lq >> 1) * 8) * ASTMH + (lq & 1) * 8) * 2);
    const unsigned int qsLd = (unsigned int)__cvta_generic_to_shared(Qs)  + aRel;
    const unsigned int psLd = (unsigned int)__cvta_generic_to_shared(Ps)  + aRel;
    const unsigned int ksLd = (unsigned int)__cvta_generic_to_shared(Ks)  + bRel;
    const unsigned int vtLd = (unsigned int)__cvta_generic_to_shared(Vts) + bRel;

    // prologue: K(0) + Q (single cp.async group)
    #pragma unroll
    for (int i = 0; i < 4; i++)
        cp_async16(ksAddr[i], K + (size_t)(base + kvRow[i]) * DMODEL + colh + kvCh[i] * 8);
    {
        unsigned int qsb = (unsigned int)__cvta_generic_to_shared(Qs);
        #pragma unroll
        for (int i = 0; i < 8; i++) {
            int c = tid + i * 128;
            int row = c >> 3, ch = c & 7;
            cp_async16(qsb + (unsigned)(row * ASTMH * 2 + ch * 16),
                       Q + (size_t)(q0 + row) * DMODEL + colh + ch * 8);
        }
    }
    CP_COMMIT();

    float o[2][8][4] = {};
    float rmax[2][2], rsum[2][2];
    #pragma unroll
    for (int mf = 0; mf < 2; mf++)
        #pragma unroll
        for (int z = 0; z < 2; z++) { rmax[mf][z] = -1e30f; rsum[mf][z] = 0.0f; }

    for (int j0 = 0; j0 < SEQ; j0 += KTILE) {
        const int kr = base + j0;

        CP_WAIT0();
        __syncthreads();                 // Ks(j) (+Q first iter) ready; Vts free

        #pragma unroll
        for (int i = 0; i < 4; i++)
            cp_async16(vsAddr[i], VtB + (size_t)kvRow[i] * 4096 + j0 + kvCh[i] * 8);
        CP_COMMIT();

        // S = Q @ K^T : per warp m32 x n64 x k64 (4 x k16)
        float s[2][8][4] = {};
        #pragma unroll
        for (int ks = 0; ks < 4; ks++) {
            const unsigned int kb = (unsigned int)ks * 32;
            unsigned a[2][4];
            ldsm_x4(a[0][0], a[0][1], a[0][2], a[0][3], qsLd + kb);
            ldsm_x4(a[1][0], a[1][1], a[1][2], a[1][3], qsLd + (unsigned)(16 * ASTMH * 2) + kb);
            #pragma unroll
            for (int p = 0; p < 4; p++) {
                unsigned b00, b01, b10, b11;
                ldsm_x4(b00, b01, b10, b11, ksLd + (unsigned)(p * 16 * ASTMH * 2) + kb);
                mma_f16(s[0][2 * p],     a[0][0], a[0][1], a[0][2], a[0][3], b00, b01);
                mma_f16(s[1][2 * p],     a[1][0], a[1][1], a[1][2], a[1][3], b00, b01);
                mma_f16(s[0][2 * p + 1], a[0][0], a[0][1], a[0][2], a[0][3], b10, b11);
                mma_f16(s[1][2 * p + 1], a[1][0], a[1][1], a[1][2], a[1][3], b10, b11);
            }
        }

        // online softmax (log2 domain; overlaps V(j) DMA)
        #pragma unroll
        for (int mf = 0; mf < 2; mf++) {
            #pragma unroll
            for (int z = 0; z < 2; z++) {
                float mx = -1e30f;
                #pragma unroll
                for (int ni = 0; ni < 8; ni++)
                    mx = fmaxf(mx, fmaxf(s[mf][ni][2 * z], s[mf][ni][2 * z + 1]));
                mx = fmaxf(mx, __shfl_xor_sync(0xffffffffu, mx, 1));
                mx = fmaxf(mx, __shfl_xor_sync(0xffffffffu, mx, 2));
                float nm   = fmaxf(rmax[mf][z], mx);
                float corr = fex2(rmax[mf][z] - nm);
                rmax[mf][z] = nm;
                float ps = 0.0f;
                #pragma unroll
                for (int ni = 0; ni < 8; ni++) {
                    float e0 = fex2(s[mf][ni][2 * z]     - nm);
                    float e1 = fex2(s[mf][ni][2 * z + 1] - nm);
                    s[mf][ni][2 * z] = e0; s[mf][ni][2 * z + 1] = e1;
                    ps += e0 + e1;
                }
                ps += __shfl_xor_sync(0xffffffffu, ps, 1);
                ps += __shfl_xor_sync(0xffffffffu, ps, 2);
                rsum[mf][z] = rsum[mf][z] * corr + ps;
                #pragma unroll
                for (int ni = 0; ni < 8; ni++) {
                    o[mf][ni][2 * z]     *= corr;
                    o[mf][ni][2 * z + 1] *= corr;
                }
            }
        }

        CP_WAIT0();
        __syncthreads();                 // Vts(j) ready; Ks free

        // write P (half2)
        #pragma unroll
        for (int mf = 0; mf < 2; mf++) {
            #pragma unroll
            for (int ni = 0; ni < 8; ni++) {
                int col = ni * 8 + 2 * cg;
                #pragma unroll
                for (int z = 0; z < 2; z++) {
                    int row = wb + mf * 16 + r + z * 8;
                    *reinterpret_cast<__half2*>(&Ps[row * ASTMH + col]) =
                        __floats2half2_rn(s[mf][ni][2 * z], s[mf][ni][2 * z + 1]);
                }
            }
        }
        __syncwarp();

        if (j0 + KTILE < SEQ) {
            #pragma unroll
            for (int i = 0; i < 4; i++)
                cp_async16(ksAddr[i], K + (size_t)(kr + KTILE + kvRow[i]) * DMODEL + colh + kvCh[i] * 8);
            CP_COMMIT();
        }

        // O += P @ V : per warp m32 x n64(d) x k64(seq)
        #pragma unroll
        for (int ks = 0; ks < 4; ks++) {
            const unsigned int kb = (unsigned int)ks * 32;
            unsigned a[2][4];
            ldsm_x4(a[0][0], a[0][1], a[0][2], a[0][3], psLd + kb);
            ldsm_x4(a[1][0], a[1][1], a[1][2], a[1][3], psLd + (unsigned)(16 * ASTMH * 2) + kb);
            #pragma unroll
            for (int p = 0; p < 4; p++) {
                unsigned b00, b01, b10, b11;
                ldsm_x4(b00, b01, b10, b11, vtLd + (unsigned)(p * 16 * ASTMH * 2) + kb);
                mma_f16(o[0][2 * p],     a[0][0], a[0][1], a[0][2], a[0][3], b00, b01);
                mma_f16(o[1][2 * p],     a[1][0], a[1][1], a[1][2], a[1][3], b00, b01);
                mma_f16(o[0][2 * p + 1], a[0][0], a[0][1], a[0][2], a[0][3], b10, b11);
                mma_f16(o[1][2 * p + 1], a[1][0], a[1][1], a[1][2], a[1][3], b10, b11);
            }
        }
    }

    // epilogue: normalize, store half
    #pragma unroll
    for (int mf = 0; mf < 2; mf++) {
        #pragma unroll
        for (int z = 0; z < 2; z++) {
            float inv = 1.0f / rsum[mf][z];
            int row = q0 + wb + mf * 16 + r + z * 8;
            #pragma unroll
            for (int ni = 0; ni < 8; ni++) {
                int col = colh + ni * 8 + 2 * cg;
                *reinterpret_cast<__half2*>(&O[(size_t)row * DMODEL + col]) =
                    __floats2half2_rn(o[mf][ni][2 * z] * inv, o[mf][ni][2 * z + 1] * inv);
            }
        }
    }
}

// ---------------- residual add + layernorm (reference form: /(std+eps)) -------
__global__ void __launch_bounds__(128)
add_ln_kernel(const float* __restrict__ A, const float* __restrict__ Bv,
              const float* __restrict__ gamma, const float* __restrict__ beta,
              float* __restrict__ out, __half* __restrict__ outh)
{
    const int row = blockIdx.x;
    const int tid = threadIdx.x;
    __shared__ float red[4];

    const float4 a4 = reinterpret_cast<const float4*>(A  + (size_t)row * DMODEL)[tid];
    const float4 b4 = reinterpret_cast<const float4*>(Bv + (size_t)row * DMODEL)[tid];
    float x0 = a4.x + b4.x, x1 = a4.y + b4.y, x2 = a4.z + b4.z, x3 = a4.w + b4.w;

    float s = x0 + x1 + x2 + x3;
    #pragma unroll
    for (int off = 16; off; off >>= 1) s += __shfl_xor_sync(0xffffffffu, s, off);
    if ((tid & 31) == 0) red[tid >> 5] = s;
    __syncthreads();
    s = red[0] + red[1] + red[2] + red[3];
    const float mean = s * (1.0f / DMODEL);

    float d0 = x0 - mean, d1 = x1 - mean, d2 = x2 - mean, d3 = x3 - mean;
    float v = d0 * d0 + d1 * d1 + d2 * d2 + d3 * d3;
    #pragma unroll
    for (int off = 16; off; off >>= 1) v += __shfl_xor_sync(0xffffffffu, v, off);
    __syncthreads();
    if ((tid & 31) == 0) red[tid >> 5] = v;
    __syncthreads();
    v = (red[0] + red[1] + red[2] + red[3]) * (1.0f / DMODEL);

    const float inv = 1.0f / (sqrtf(v) + EPS);
    const float4 g4  = reinterpret_cast<const float4*>(gamma)[tid];
    const float4 be4 = reinterpret_cast<const float4*>(beta )[tid];
    float4 o4;
    o4.x = d0 * inv * g4.x + be4.x;
    o4.y = d1 * inv * g4.y + be4.y;
    o4.z = d2 * inv * g4.z + be4.z;
    o4.w = d3 * inv * g4.w + be4.w;
    reinterpret_cast<float4*>(out + (size_t)row * DMODEL)[tid] = o4;
    if (outh != 0) {
        *reinterpret_cast<__half2*>(outh + (size_t)row * DMODEL + tid * 4)     = __floats2half2_rn(o4.x, o4.y);
        *reinterpret_cast<__half2*>(outh + (size_t)row * DMODEL + tid * 4 + 2) = __floats2half2_rn(o4.z, o4.w);
    }
}

// ---------------- host launch --------------------------------------------------
extern "C" void kernel_launch(void* const* d_in, const int* in_sizes, int n_in,
                              void* d_out, int out_size)
{
    const float* x   = (const float*)d_in[0];
    const float* Wq  = (const float*)d_in[1];
    const float* bq  = (const float*)d_in[2];
    const float* Wk  = (const float*)d_in[3];
    const float* bk  = (const float*)d_in[4];
    const float* Wv  = (const float*)d_in[5];
    const float* bv  = (const float*)d_in[6];
    const float* Wo  = (const float*)d_in[7];
    const float* bo  = (const float*)d_in[8];
    const float* W1  = (const float*)d_in[9];
    const float* b1  = (const float*)d_in[10];
    const float* W2  = (const float*)d_in[11];
    const float* b2  = (const float*)d_in[12];
    const float* g1  = (const float*)d_in[13];
    const float* be1 = (const float*)d_in[14];
    const float* g2  = (const float*)d_in[15];
    const float* be2 = (const float*)d_in[16];
    float* out = (float*)d_out;

    __half *Qh, *Kh, *Vt, *AOh, *xh, *X1h, *FFHh, *Wh;
    float *X1, *tmp;
    cudaGetSymbolAddress((void**)&Qh,   g_Qh);
    cudaGetSymbolAddress((void**)&Kh,   g_Kh);
    cudaGetSymbolAddress((void**)&Vt,   g_Vt);
    cudaGetSymbolAddress((void**)&AOh,  g_AOh);
    cudaGetSymbolAddress((void**)&xh,   g_xh);
    cudaGetSymbolAddress((void**)&X1h,  g_X1h);
    cudaGetSymbolAddress((void**)&FFHh, g_FFHh);
    cudaGetSymbolAddress((void**)&Wh,   g_Wh);
    cudaGetSymbolAddress((void**)&X1,   g_X1);
    cudaGetSymbolAddress((void**)&tmp,  g_tmp);

    __half* Woh = Wh + 3 * WSEG1;
    __half* W1h = Wh + 4 * WSEG1;               // [2048][512]
    __half* W2h = Wh + 4 * WSEG1 + WSEG2;       // [512][2048]

    cudaFuncSetAttribute(attn_h,      cudaFuncAttributeMaxDynamicSharedMemorySize, ATT_SMEM);
    cudaFuncSetAttribute(gemm_f32,    cudaFuncAttributeMaxDynamicSharedMemorySize, GEMM_SMEM);
    cudaFuncSetAttribute(gemm_h_relu, cudaFuncAttributeMaxDynamicSharedMemorySize, GEMM_SMEM);
    cudaFuncSetAttribute(qkv_h,       cudaFuncAttributeMaxDynamicSharedMemorySize, GEMM_SMEM);

    const dim3 t256(256), t128(128);

    // weight prep: half + transpose to [N][K]
    wprep_h<<<dim3(DMODEL / 32, DMODEL / 32), t256>>>(Wq, Wh,             DMODEL, DMODEL);
    wprep_h<<<dim3(DMODEL / 32, DMODEL / 32), t256>>>(Wk, Wh + 1 * WSEG1, DMODEL, DMODEL);
    wprep_h<<<dim3(DMODEL / 32, DMODEL / 32), t256>>>(Wv, Wh + 2 * WSEG1, DMODEL, DMODEL);
    wprep_h<<<dim3(DMODEL / 32, DMODEL / 32), t256>>>(Wo, Woh,            DMODEL, DMODEL);
    wprep_h<<<dim3(DFF / 32,    DMODEL / 32), t256>>>(W1, W1h,            DMODEL, DFF);
    wprep_h<<<dim3(DMODEL / 32, DFF / 32),    t256>>>(W2, W2h,            DFF,    DMODEL);

    // input -> half
    xconv<<<(ROWS * DMODEL / 4) / 256, t256>>>(x, xh);

    // QKV projections (fused fp16 launch)
    qkv_h<<<dim3(DMODEL / TBN, ROWS / TBM, 3), t256, GEMM_SMEM>>>(
        xh, Wh, bq, bk, bv, Qh, Kh, Vt);

    // attention
    attn_h<<<dim3(SEQ / QTILE, BATCH * NHEADS), t128, ATT_SMEM>>>(Qh, Kh, Vt, AOh);

    // output projection + LN1 (dual output: fp32 residual + half for FFN1)
    gemm_f32<<<dim3(DMODEL / TBN, ROWS / TBM), t256, GEMM_SMEM>>>(AOh, Woh, bo, tmp, DMODEL, DMODEL);
    add_ln_kernel<<<ROWS, 128>>>(x, tmp, g1, be1, X1, X1h);

    // FFN
    gemm_h_relu<<<dim3(DFF / TBN, ROWS / TBM), t256, GEMM_SMEM>>>(X1h, W1h, b1, FFHh, DFF, DMODEL);
    gemm_f32<<<dim3(DMODEL / TBN, ROWS / TBM), t256, GEMM_SMEM>>>(FFHh, W2h, b2, tmp, DMODEL, DFF);

    // LN2 -> final output
    add_ln_kernel<<<ROWS, 128>>>(X1, tmp, g2, be2, out, (__half*)0);
}

// round 17
// speedup vs baseline: 2.0069x; 1.1119x over previous
#include <cuda_runtime.h>
#include <cuda_fp16.h>
#include <math.h>
#include <stdint.h>

#define BATCH   2
#define SEQ     4096
#define DMODEL  512
#define NHEADS  8
#define DK      64
#define DFF     2048
#define ROWS    (BATCH * SEQ)   // 8192
#define EPS     1e-5f
#define WSEG1 (DMODEL * DMODEL)          // 262144
#define WSEG2 (DMODEL * DFF)             // 1048576

// ---------------- scratch (static device globals; no allocs allowed) ----------
__device__ __half g_Qh [ROWS * DMODEL];     // Q proj, pre-scaled, half
__device__ __half g_Kh [ROWS * DMODEL];     // K proj, half [seq][d]
__device__ __half g_Vt [ROWS * DMODEL];     // V proj, half, [bh][d][seq]
__device__ __half g_AOh[ROWS * DMODEL];     // attn out, half
__device__ __half g_xh [ROWS * DMODEL];     // input x, half
__device__ __half g_X1h[ROWS * DMODEL];     // post-LN1, half
__device__ __half g_FFHh[ROWS * DFF];       // FFN hidden, half
__device__ float  g_X1 [ROWS * DMODEL];     // post-LN1, fp32 (residual)
__device__ float  g_tmp[ROWS * DMODEL];     // fp32 GEMM outputs
__device__ __half g_Wh [4 * WSEG1 + 2 * WSEG2];  // weights, half, [N][K] layout

// ---------------- helpers -------------------------------------------------------
__device__ __forceinline__ float fex2(float x) {
    float y;
    asm("ex2.approx.f32 %0, %1;" : "=f"(y) : "f"(x));
    return y;
}

__device__ __forceinline__ void mma_f16(float* c,
                                        unsigned a0, unsigned a1, unsigned a2, unsigned a3,
                                        unsigned b0, unsigned b1)
{
    asm volatile(
        "mma.sync.aligned.m16n8k16.row.col.f32.f16.f16.f32 "
        "{%0,%1,%2,%3}, {%4,%5,%6,%7}, {%8,%9}, {%0,%1,%2,%3};"
        : "+f"(c[0]), "+f"(c[1]), "+f"(c[2]), "+f"(c[3])
        : "r"(a0), "r"(a1), "r"(a2), "r"(a3), "r"(b0), "r"(b1));
}

__device__ __forceinline__ void ldsm_x4(unsigned& r0, unsigned& r1, unsigned& r2, unsigned& r3,
                                        unsigned int addr)
{
    asm volatile("ldmatrix.sync.aligned.m8n8.x4.shared.b16 {%0,%1,%2,%3}, [%4];"
                 : "=r"(r0), "=r"(r1), "=r"(r2), "=r"(r3) : "r"(addr));
}

__device__ __forceinline__ void cp_async16(unsigned int smem_addr, const void* gptr) {
    asm volatile("cp.async.cg.shared.global [%0], [%1], 16;"
                 :: "r"(smem_addr), "l"(gptr));
}
#define CP_COMMIT() asm volatile("cp.async.commit_group;")
#define CP_WAIT0()  asm volatile("cp.async.wait_group 0;")

// ---------------- fused weight prep: all 6 matrices, one launch ----------------
// out[N][K] = half(in[K][N])^T per segment; flat 32x32-tile index.
// tiles: Wq/Wk/Wv/Wo 256 each (0..1023), W1 1024 (1024..2047), W2 1024 (2048..3071)
__global__ void __launch_bounds__(256)
wprep_all(const float* __restrict__ Wq, const float* __restrict__ Wk,
          const float* __restrict__ Wv, const float* __restrict__ Wo,
          const float* __restrict__ W1, const float* __restrict__ W2,
          __half* __restrict__ outbase)
{
    const int t = blockIdx.x;
    const float* in;
    __half* out;
    int K, N, n0, k0;
    if (t < 1024) {
        int z = t >> 8, idx = t & 255;
        const float* srcs[4] = {Wq, Wk, Wv, Wo};
        in = srcs[z];
        out = outbase + (size_t)z * WSEG1;
        K = DMODEL; N = DMODEL;
        n0 = (idx & 15) * 32; k0 = (idx >> 4) * 32;
    } else if (t < 2048) {
        int idx = t - 1024;
        in = W1; out = outbase + 4 * (size_t)WSEG1;
        K = DMODEL; N = DFF;
        n0 = (idx & 63) * 32; k0 = (idx >> 6) * 32;
    } else {
        int idx = t - 2048;
        in = W2; out = outbase + 4 * (size_t)WSEG1 + WSEG2;
        K = DFF; N = DMODEL;
        n0 = (idx & 15) * 32; k0 = (idx >> 4) * 32;
    }

    __shared__ float tt[32][33];
    const int tx = threadIdx.x & 31, ty = threadIdx.x >> 5;  // (32, 8)
    #pragma unroll
    for (int i = 0; i < 4; i++)
        tt[ty + 8 * i][tx] = in[(size_t)(k0 + ty + 8 * i) * N + n0 + tx];
    __syncthreads();
    #pragma unroll
    for (int i = 0; i < 4; i++)
        out[(size_t)(n0 + ty + 8 * i) * K + k0 + tx] = __float2half_rn(tt[tx][ty + 8 * i]);
}

// ---------------- x -> half -----------------------------------------------------
__global__ void __launch_bounds__(256)
xconv(const float* __restrict__ in, __half* __restrict__ out)
{
    size_t i = (size_t)blockIdx.x * 256 + threadIdx.x;   // float4 index
    float4 v = reinterpret_cast<const float4*>(in)[i];
    *reinterpret_cast<__half2*>(out + i * 4)     = __floats2half2_rn(v.x, v.y);
    *reinterpret_cast<__half2*>(out + i * 4 + 2) = __floats2half2_rn(v.z, v.w);
}

// ---------------- fp16 GEMM mainloop: acc = A[M,K] @ Bt[N,K]^T ------------------
// block tile 128x128x64, 256 threads, warps 2(m) x 4(n), warp tile 64x32
#define TBM 128
#define TBN 128
#define TBKH 64
#define STRH 72
#define STGB ((TBM * STRH + TBN * STRH) * 2)     // 36864 bytes per stage
#define GEMM_SMEM (2 * STGB)                     // 73728 -> 2 CTAs/SM

__device__ __forceinline__ void gemm_main(
    const __half* __restrict__ A, const __half* __restrict__ Bt,
    int K, int row0, int col0, float acc[4][4][4])
{
    extern __shared__ __half hsm[];

    const int tid  = threadIdx.x;
    const int warp = tid >> 5, lane = tid & 31;
    const int wm = warp >> 2;          // 0..1
    const int wn = warp & 3;           // 0..3
    const int lq = lane >> 3;          // 0..3 (ldmatrix quad)
    const int lr = lane & 7;           // 0..7 (ldmatrix row)

    int tRow[4], tCh[4];
    unsigned int sOff[4];
    #pragma unroll
    for (int i = 0; i < 4; i++) {
        int c = tid + i * 256;
        tRow[i] = c >> 3;
        tCh[i]  = c & 7;
        sOff[i] = (unsigned int)(tRow[i] * STRH * 2 + tCh[i] * 16);
    }
    const unsigned int smemBase = (unsigned int)__cvta_generic_to_shared(hsm);

    const unsigned int aOffL = (unsigned int)(((wm * 64 + lr + (lq & 1) * 8) * STRH + (lq >> 1) * 8) * 2);
    const unsigned int bOffL = (unsigned int)(TBM * STRH * 2 +
                               ((wn * 32 + lr + (lq >> 1) * 8) * STRH + (lq & 1) * 8) * 2);

    auto issue = [&](int stg, int k0) {
        unsigned int sb = smemBase + (unsigned int)stg * STGB;
        #pragma unroll
        for (int i = 0; i < 4; i++) {
            cp_async16(sb + sOff[i],
                       A + (size_t)(row0 + tRow[i]) * K + k0 + tCh[i] * 8);
            cp_async16(sb + (unsigned int)(TBM * STRH * 2) + sOff[i],
                       Bt + (size_t)(col0 + tRow[i]) * K + k0 + tCh[i] * 8);
        }
        CP_COMMIT();
    };

    const int NT = K / TBKH;
    issue(0, 0);

    for (int kt = 0; kt < NT; kt++) {
        const int cur = kt & 1;
        CP_WAIT0();
        __syncthreads();

        if (kt + 1 < NT) issue(cur ^ 1, (kt + 1) * TBKH);

        const unsigned int stB = smemBase + (unsigned int)cur * STGB;
        const unsigned int aB = stB + aOffL;
        const unsigned int bB = stB + bOffL;

        #pragma unroll
        for (int ks = 0; ks < 4; ks++) {
            const unsigned int kb = (unsigned int)ks * 32;   // 16 halves
            unsigned a[4][4];
            #pragma unroll
            for (int mi = 0; mi < 4; mi++)
                ldsm_x4(a[mi][0], a[mi][1], a[mi][2], a[mi][3],
                        aB + (unsigned int)(mi * 16 * STRH * 2) + kb);
            #pragma unroll
            for (int p = 0; p < 2; p++) {
                unsigned b00, b01, b10, b11;
                ldsm_x4(b00, b01, b10, b11, bB + (unsigned int)(p * 16 * STRH * 2) + kb);
                #pragma unroll
                for (int mi = 0; mi < 4; mi++) {
                    mma_f16(acc[mi][2 * p],     a[mi][0], a[mi][1], a[mi][2], a[mi][3], b00, b01);
                    mma_f16(acc[mi][2 * p + 1], a[mi][0], a[mi][1], a[mi][2], a[mi][3], b10, b11);
                }
            }
        }
    }
}

// fp32-output GEMM (Wo proj, FFN2)
__global__ void __launch_bounds__(256, 2)
gemm_f32(const __half* __restrict__ A, const __half* __restrict__ Bt,
         const float* __restrict__ bias, float* __restrict__ C, int N, int K)
{
    const int row0 = blockIdx.y * TBM, col0 = blockIdx.x * TBN;
    float acc[4][4][4] = {};
    gemm_main(A, Bt, K, row0, col0, acc);

    const int tid = threadIdx.x, warp = tid >> 5, lane = tid & 31;
    const int wm = warp >> 2, wn = warp & 3, r = lane >> 2, cg = lane & 3;
    #pragma unroll
    for (int mi = 0; mi < 4; mi++) {
        int mb = row0 + wm * 64 + mi * 16;
        #pragma unroll
        for (int ni = 0; ni < 4; ni++) {
            int col = col0 + wn * 32 + ni * 8 + 2 * cg;
            float bs0 = bias[col], bs1 = bias[col + 1];
            #pragma unroll
            for (int hf = 0; hf < 2; hf++) {
                int row = mb + r + hf * 8;
                *reinterpret_cast<float2*>(&C[(size_t)row * N + col]) =
                    make_float2(acc[mi][ni][2 * hf] + bs0, acc[mi][ni][2 * hf + 1] + bs1);
            }
        }
    }
}

// half-output + relu GEMM (FFN1)
__global__ void __launch_bounds__(256, 2)
gemm_h_relu(const __half* __restrict__ A, const __half* __restrict__ Bt,
            const float* __restrict__ bias, __half* __restrict__ Ch, int N, int K)
{
    const int row0 = blockIdx.y * TBM, col0 = blockIdx.x * TBN;
    float acc[4][4][4] = {};
    gemm_main(A, Bt, K, row0, col0, acc);

    const int tid = threadIdx.x, warp = tid >> 5, lane = tid & 31;
    const int wm = warp >> 2, wn = warp & 3, r = lane >> 2, cg = lane & 3;
    #pragma unroll
    for (int mi = 0; mi < 4; mi++) {
        int mb = row0 + wm * 64 + mi * 16;
        #pragma unroll
        for (int ni = 0; ni < 4; ni++) {
            int col = col0 + wn * 32 + ni * 8 + 2 * cg;
            float bs0 = bias[col], bs1 = bias[col + 1];
            #pragma unroll
            for (int hf = 0; hf < 2; hf++) {
                int row = mb + r + hf * 8;
                float v0 = fmaxf(acc[mi][ni][2 * hf]     + bs0, 0.0f);
                float v1 = fmaxf(acc[mi][ni][2 * hf + 1] + bs1, 0.0f);
                *reinterpret_cast<__half2*>(&Ch[(size_t)row * N + col]) = __floats2half2_rn(v0, v1);
            }
        }
    }
}

// fused QKV: z=0 -> Qh (scaled), z=1 -> Kh, z=2 -> Vt (transposed [bh][d][seq])
#define QSCALE 0.18033688011f   // 0.125 * log2(e)
__global__ void __launch_bounds__(256, 2)
qkv_h(const __half* __restrict__ xh, const __half* __restrict__ Wh,
      const float* __restrict__ bq, const float* __restrict__ bk, const float* __restrict__ bv,
      __half* __restrict__ Qh, __half* __restrict__ Kh, __half* __restrict__ Vt)
{
    const int z = blockIdx.z;
    const __half* Bt = Wh + (size_t)z * WSEG1;
    const float* bias = (z == 0) ? bq : (z == 1) ? bk : bv;
    const int row0 = blockIdx.y * TBM, col0 = blockIdx.x * TBN;

    float acc[4][4][4] = {};
    gemm_main(xh, Bt, DMODEL, row0, col0, acc);

    const int tid = threadIdx.x, warp = tid >> 5, lane = tid & 31;
    const int wm = warp >> 2, wn = warp & 3, r = lane >> 2, cg = lane & 3;
    #pragma unroll
    for (int mi = 0; mi < 4; mi++) {
        int mb = row0 + wm * 64 + mi * 16;
        #pragma unroll
        for (int ni = 0; ni < 4; ni++) {
            int col = col0 + wn * 32 + ni * 8 + 2 * cg;
            float bs0 = bias[col], bs1 = bias[col + 1];
            #pragma unroll
            for (int hf = 0; hf < 2; hf++) {
                int row = mb + r + hf * 8;
                float v0 = acc[mi][ni][2 * hf]     + bs0;
                float v1 = acc[mi][ni][2 * hf + 1] + bs1;
                if (z == 0) {
                    *reinterpret_cast<__half2*>(&Qh[(size_t)row * DMODEL + col]) =
                        __floats2half2_rn(v0 * QSCALE, v1 * QSCALE);
                } else if (z == 1) {
                    *reinterpret_cast<__half2*>(&Kh[(size_t)row * DMODEL + col]) =
                        __floats2half2_rn(v0, v1);
                } else {
                    int bh  = (row >> 12) * 8 + (col >> 6);
                    int d   = col & 63;
                    int seq = row & 4095;
                    size_t bbase = (size_t)bh * (64 * 4096) + (size_t)d * 4096 + seq;
                    Vt[bbase]        = __float2half_rn(v0);
                    Vt[bbase + 4096] = __float2half_rn(v1);
                }
            }
        }
    }
}

// ---------------- flash attention, fp16 mma + ldmatrix --------------------------
#define QTILE 128
#define KTILE 64
#define ASTMH 72
#define ATT_SMEM ((QTILE * ASTMH + KTILE * ASTMH + KTILE * ASTMH + QTILE * ASTMH) * 2)

__global__ void __launch_bounds__(128, 2)
attn_h(const __half* __restrict__ Q, const __half* __restrict__ K,
       const __half* __restrict__ Vt, __half* __restrict__ O)
{
    extern __shared__ __half ash[];
    __half* Qs  = ash;                       // [128][72]
    __half* Ks  = Qs + QTILE * ASTMH;        // [64][72]  ([seq][d])
    __half* Vts = Ks + KTILE * ASTMH;        // [64][72]  ([d][seq])
    __half* Ps  = Vts + KTILE * ASTMH;       // [128][72] ([qrow][seq])

    const int tid  = threadIdx.x;
    const int warp = tid >> 5, lane = tid & 31;
    const int r    = lane >> 2;
    const int cg   = lane & 3;
    const int lq   = lane >> 3;              // ldmatrix quad
    const int lr   = lane & 7;               // ldmatrix row
    const int wb   = warp * 32;

    const int qt = blockIdx.x;
    const int bh = blockIdx.y;
    const int b  = bh >> 3, h = bh & 7;
    const int base = b * SEQ;
    const int q0   = base + qt * QTILE;
    const int colh = h * DK;
    const __half* VtB = Vt + (size_t)bh * (64 * 4096);

    int kvRow[4], kvCh[4];
    unsigned int ksAddr[4], vsAddr[4];
    #pragma unroll
    for (int i = 0; i < 4; i++) {
        int c = tid + i * 128;
        kvRow[i] = c >> 3;
        kvCh[i]  = c & 7;
        unsigned off = (unsigned)(kvRow[i] * ASTMH * 2 + kvCh[i] * 16);
        ksAddr[i] = (unsigned int)__cvta_generic_to_shared(Ks)  + off;
        vsAddr[i] = (unsigned int)__cvta_generic_to_shared(Vts) + off;
    }

    const unsigned int aRel = (unsigned int)(((wb + lr + (lq & 1) * 8) * ASTMH + (lq >> 1) * 8) * 2);
    const unsigned int bRel = (unsigned int)(((lr + (lq >> 1) * 8) * ASTMH + (lq & 1) * 8) * 2);
    const unsigned int qsLd = (unsigned int)__cvta_generic_to_shared(Qs)  + aRel;
    const unsigned int psLd = (unsigned int)__cvta_generic_to_shared(Ps)  + aRel;
    const unsigned int ksLd = (unsigned int)__cvta_generic_to_shared(Ks)  + bRel;
    const unsigned int vtLd = (unsigned int)__cvta_generic_to_shared(Vts) + bRel;

    // prologue: K(0) + Q (single cp.async group)
    #pragma unroll
    for (int i = 0; i < 4; i++)
        cp_async16(ksAddr[i], K + (size_t)(base + kvRow[i]) * DMODEL + colh + kvCh[i] * 8);
    {
        unsigned int qsb = (unsigned int)__cvta_generic_to_shared(Qs);
        #pragma unroll
        for (int i = 0; i < 8; i++) {
            int c = tid + i * 128;
            int row = c >> 3, ch = c & 7;
            cp_async16(qsb + (unsigned)(row * ASTMH * 2 + ch * 16),
                       Q + (size_t)(q0 + row) * DMODEL + colh + ch * 8);
        }
    }
    CP_COMMIT();

    float o[2][8][4] = {};
    float rmax[2][2], rsum[2][2];
    #pragma unroll
    for (int mf = 0; mf < 2; mf++)
        #pragma unroll
        for (int z = 0; z < 2; z++) { rmax[mf][z] = -1e30f; rsum[mf][z] = 0.0f; }

    for (int j0 = 0; j0 < SEQ; j0 += KTILE) {
        const int kr = base + j0;

        CP_WAIT0();
        __syncthreads();                 // Ks(j) (+Q first iter) ready; Vts free

        #pragma unroll
        for (int i = 0; i < 4; i++)
            cp_async16(vsAddr[i], VtB + (size_t)kvRow[i] * 4096 + j0 + kvCh[i] * 8);
        CP_COMMIT();

        // S = Q @ K^T : per warp m32 x n64 x k64 (4 x k16)
        float s[2][8][4] = {};
        #pragma unroll
        for (int ks = 0; ks < 4; ks++) {
            const unsigned int kb = (unsigned int)ks * 32;
            unsigned a[2][4];
            ldsm_x4(a[0][0], a[0][1], a[0][2], a[0][3], qsLd + kb);
            ldsm_x4(a[1][0], a[1][1], a[1][2], a[1][3], qsLd + (unsigned)(16 * ASTMH * 2) + kb);
            #pragma unroll
            for (int p = 0; p < 4; p++) {
                unsigned b00, b01, b10, b11;
                ldsm_x4(b00, b01, b10, b11, ksLd + (unsigned)(p * 16 * ASTMH * 2) + kb);
                mma_f16(s[0][2 * p],     a[0][0], a[0][1], a[0][2], a[0][3], b00, b01);
                mma_f16(s[1][2 * p],     a[1][0], a[1][1], a[1][2], a[1][3], b00, b01);
                mma_f16(s[0][2 * p + 1], a[0][0], a[0][1], a[0][2], a[0][3], b10, b11);
                mma_f16(s[1][2 * p + 1], a[1][0], a[1][1], a[1][2], a[1][3], b10, b11);
            }
        }

        // online softmax (log2 domain; overlaps V(j) DMA)
        #pragma unroll
        for (int mf = 0; mf < 2; mf++) {
            #pragma unroll
            for (int z = 0; z < 2; z++) {
                float mx = -1e30f;
                #pragma unroll
                for (int ni = 0; ni < 8; ni++)
                    mx = fmaxf(mx, fmaxf(s[mf][ni][2 * z], s[mf][ni][2 * z + 1]));
                mx = fmaxf(mx, __shfl_xor_sync(0xffffffffu, mx, 1));
                mx = fmaxf(mx, __shfl_xor_sync(0xffffffffu, mx, 2));
                float nm   = fmaxf(rmax[mf][z], mx);
                float corr = fex2(rmax[mf][z] - nm);
                rmax[mf][z] = nm;
                float ps = 0.0f;
                #pragma unroll
                for (int ni = 0; ni < 8; ni++) {
                    float e0 = fex2(s[mf][ni][2 * z]     - nm);
                    float e1 = fex2(s[mf][ni][2 * z + 1] - nm);
                    s[mf][ni][2 * z] = e0; s[mf][ni][2 * z + 1] = e1;
                    ps += e0 + e1;
                }
                ps += __shfl_xor_sync(0xffffffffu, ps, 1);
                ps += __shfl_xor_sync(0xffffffffu, ps, 2);
                rsum[mf][z] = rsum[mf][z] * corr + ps;
                #pragma unroll
                for (int ni = 0; ni < 8; ni++) {
                    o[mf][ni][2 * z]     *= corr;
                    o[mf][ni][2 * z + 1] *= corr;
                }
            }
        }

        // write P (half2) BEFORE waiting on V — overlaps store latency with V DMA
        #pragma unroll
        for (int mf = 0; mf < 2; mf++) {
            #pragma unroll
            for (int ni = 0; ni < 8; ni++) {
                int col = ni * 8 + 2 * cg;
                #pragma unroll
                for (int z = 0; z < 2; z++) {
                    int row = wb + mf * 16 + r + z * 8;
                    *reinterpret_cast<__half2*>(&Ps[row * ASTMH + col]) =
                        __floats2half2_rn(s[mf][ni][2 * z], s[mf][ni][2 * z + 1]);
                }
            }
        }

        CP_WAIT0();
        __syncthreads();                 // Vts(j) ready; all warps past S(j) -> Ks free

        if (j0 + KTILE < SEQ) {
            #pragma unroll
            for (int i = 0; i < 4; i++)
                cp_async16(ksAddr[i], K + (size_t)(kr + KTILE + kvRow[i]) * DMODEL + colh + kvCh[i] * 8);
            CP_COMMIT();
        }

        // O += P @ V : per warp m32 x n64(d) x k64(seq)
        #pragma unroll
        for (int ks = 0; ks < 4; ks++) {
            const unsigned int kb = (unsigned int)ks * 32;
            unsigned a[2][4];
            ldsm_x4(a[0][0], a[0][1], a[0][2], a[0][3], psLd + kb);
            ldsm_x4(a[1][0], a[1][1], a[1][2], a[1][3], psLd + (unsigned)(16 * ASTMH * 2) + kb);
            #pragma unroll
            for (int p = 0; p < 4; p++) {
                unsigned b00, b01, b10, b11;
                ldsm_x4(b00, b01, b10, b11, vtLd + (unsigned)(p * 16 * ASTMH * 2) + kb);
                mma_f16(o[0][2 * p],     a[0][0], a[0][1], a[0][2], a[0][3], b00, b01);
                mma_f16(o[1][2 * p],     a[1][0], a[1][1], a[1][2], a[1][3], b00, b01);
                mma_f16(o[0][2 * p + 1], a[0][0], a[0][1], a[0][2], a[0][3], b10, b11);
                mma_f16(o[1][2 * p + 1], a[1][0], a[1][1], a[1][2], a[1][3], b10, b11);
            }
        }
    }

    // epilogue: normalize, store half
    #pragma unroll
    for (int mf = 0; mf < 2; mf++) {
        #pragma unroll
        for (int z = 0; z < 2; z++) {
            float inv = 1.0f / rsum[mf][z];
            int row = q0 + wb + mf * 16 + r + z * 8;
            #pragma unroll
            for (int ni = 0; ni < 8; ni++) {
                int col = colh + ni * 8 + 2 * cg;
                *reinterpret_cast<__half2*>(&O[(size_t)row * DMODEL + col]) =
                    __floats2half2_rn(o[mf][ni][2 * z] * inv, o[mf][ni][2 * z + 1] * inv);
            }
        }
    }
}

// ---------------- residual add + layernorm (reference form: /(std+eps)) -------
__global__ void __launch_bounds__(128)
add_ln_kernel(const float* __restrict__ A, const float* __restrict__ Bv,
              const float* __restrict__ gamma, const float* __restrict__ beta,
              float* __restrict__ out, __half* __restrict__ outh)
{
    const int row = blockIdx.x;
    const int tid = threadIdx.x;
    __shared__ float red[4];

    const float4 a4 = reinterpret_cast<const float4*>(A  + (size_t)row * DMODEL)[tid];
    const float4 b4 = reinterpret_cast<const float4*>(Bv + (size_t)row * DMODEL)[tid];
    float x0 = a4.x + b4.x, x1 = a4.y + b4.y, x2 = a4.z + b4.z, x3 = a4.w + b4.w;

    float s = x0 + x1 + x2 + x3;
    #pragma unroll
    for (int off = 16; off; off >>= 1) s += __shfl_xor_sync(0xffffffffu, s, off);
    if ((tid & 31) == 0) red[tid >> 5] = s;
    __syncthreads();
    s = red[0] + red[1] + red[2] + red[3];
    const float mean = s * (1.0f / DMODEL);

    float d0 = x0 - mean, d1 = x1 - mean, d2 = x2 - mean, d3 = x3 - mean;
    float v = d0 * d0 + d1 * d1 + d2 * d2 + d3 * d3;
    #pragma unroll
    for (int off = 16; off; off >>= 1) v += __shfl_xor_sync(0xffffffffu, v, off);
    __syncthreads();
    if ((tid & 31) == 0) red[tid >> 5] = v;
    __syncthreads();
    v = (red[0] + red[1] + red[2] + red[3]) * (1.0f / DMODEL);

    const float inv = 1.0f / (sqrtf(v) + EPS);
    const float4 g4  = reinterpret_cast<const float4*>(gamma)[tid];
    const float4 be4 = reinterpret_cast<const float4*>(beta )[tid];
    float4 o4;
    o4.x = d0 * inv * g4.x + be4.x;
    o4.y = d1 * inv * g4.y + be4.y;
    o4.z = d2 * inv * g4.z + be4.z;
    o4.w = d3 * inv * g4.w + be4.w;
    reinterpret_cast<float4*>(out + (size_t)row * DMODEL)[tid] = o4;
    if (outh != 0) {
        *reinterpret_cast<__half2*>(outh + (size_t)row * DMODEL + tid * 4)     = __floats2half2_rn(o4.x, o4.y);
        *reinterpret_cast<__half2*>(outh + (size_t)row * DMODEL + tid * 4 + 2) = __floats2half2_rn(o4.z, o4.w);
    }
}

// ---------------- host launch --------------------------------------------------
extern "C" void kernel_launch(void* const* d_in, const int* in_sizes, int n_in,
                              void* d_out, int out_size)
{
    const float* x   = (const float*)d_in[0];
    const float* Wq  = (const float*)d_in[1];
    const float* bq  = (const float*)d_in[2];
    const float* Wk  = (const float*)d_in[3];
    const float* bk  = (const float*)d_in[4];
    const float* Wv  = (const float*)d_in[5];
    const float* bv  = (const float*)d_in[6];
    const float* Wo  = (const float*)d_in[7];
    const float* bo  = (const float*)d_in[8];
    const float* W1  = (const float*)d_in[9];
    const float* b1  = (const float*)d_in[10];
    const float* W2  = (const float*)d_in[11];
    const float* b2  = (const float*)d_in[12];
    const float* g1  = (const float*)d_in[13];
    const float* be1 = (const float*)d_in[14];
    const float* g2  = (const float*)d_in[15];
    const float* be2 = (const float*)d_in[16];
    float* out = (float*)d_out;

    __half *Qh, *Kh, *Vt, *AOh, *xh, *X1h, *FFHh, *Wh;
    float *X1, *tmp;
    cudaGetSymbolAddress((void**)&Qh,   g_Qh);
    cudaGetSymbolAddress((void**)&Kh,   g_Kh);
    cudaGetSymbolAddress((void**)&Vt,   g_Vt);
    cudaGetSymbolAddress((void**)&AOh,  g_AOh);
    cudaGetSymbolAddress((void**)&xh,   g_xh);
    cudaGetSymbolAddress((void**)&X1h,  g_X1h);
    cudaGetSymbolAddress((void**)&FFHh, g_FFHh);
    cudaGetSymbolAddress((void**)&Wh,   g_Wh);
    cudaGetSymbolAddress((void**)&X1,   g_X1);
    cudaGetSymbolAddress((void**)&tmp,  g_tmp);

    __half* Woh = Wh + 3 * WSEG1;
    __half* W1h = Wh + 4 * WSEG1;               // [2048][512]
    __half* W2h = Wh + 4 * WSEG1 + WSEG2;       // [512][2048]

    cudaFuncSetAttribute(attn_h,      cudaFuncAttributeMaxDynamicSharedMemorySize, ATT_SMEM);
    cudaFuncSetAttribute(gemm_f32,    cudaFuncAttributeMaxDynamicSharedMemorySize, GEMM_SMEM);
    cudaFuncSetAttribute(gemm_h_relu, cudaFuncAttributeMaxDynamicSharedMemorySize, GEMM_SMEM);
    cudaFuncSetAttribute(qkv_h,       cudaFuncAttributeMaxDynamicSharedMemorySize, GEMM_SMEM);

    const dim3 t256(256), t128(128);

    // weight prep: all six matrices, one launch
    wprep_all<<<3072, t256>>>(Wq, Wk, Wv, Wo, W1, W2, Wh);

    // input -> half
    xconv<<<(ROWS * DMODEL / 4) / 256, t256>>>(x, xh);

    // QKV projections (fused fp16 launch)
    qkv_h<<<dim3(DMODEL / TBN, ROWS / TBM, 3), t256, GEMM_SMEM>>>(
        xh, Wh, bq, bk, bv, Qh, Kh, Vt);

    // attention
    attn_h<<<dim3(SEQ / QTILE, BATCH * NHEADS), t128, ATT_SMEM>>>(Qh, Kh, Vt, AOh);

    // output projection + LN1 (dual output: fp32 residual + half for FFN1)
    gemm_f32<<<dim3(DMODEL / TBN, ROWS / TBM), t256, GEMM_SMEM>>>(AOh, Woh, bo, tmp, DMODEL, DMODEL);
    add_ln_kernel<<<ROWS, 128>>>(x, tmp, g1, be1, X1, X1h);

    // FFN
    gemm_h_relu<<<dim3(DFF / TBN, ROWS / TBM), t256, GEMM_SMEM>>>(X1h, W1h, b1, FFHh, DFF, DMODEL);
    gemm_f32<<<dim3(DMODEL / TBN, ROWS / TBM), t256, GEMM_SMEM>>>(FFHh, W2h, b2, tmp, DMODEL, DFF);

    // LN2 -> final output
    add_ln_kernel<<<ROWS, 128>>>(X1, tmp, g2, be2, out, (__half*)0);
}